// round 7
// baseline (speedup 1.0000x reference)
#include <cuda_runtime.h>
#include <math.h>
#include <stdint.h>

// Problem constants
#define NB 8
#define NC 128
#define NHW 16384
#define NE 4
#define NR 64

// smem layout (words) for main kernel
#define LDA 136           // weight (A-operand) row stride, fragment-packed k layout
#define LDB 140           // activation (B-operand) row stride, n-interleaved layout
#define SM_X 0
#define SM_S (128 * LDB)
#define SM_W (2 * 128 * LDB)
#define SMEM_MAIN ((2 * 128 * LDB + 128 * LDA) * 4)   // 212992 bytes

// ---------------- device scratch ----------------
__device__ float g_fe0[NB * NC];
__device__ float g_pooled[NB * NC];
__device__ int   g_sel[NB * 2];
__device__ float g_gate[NB * 2];
__device__ float g_gsum[NB];
__device__ float g_PW2[NE * NC * NR];   // proj_w @ exp_w2[e] : [e][d][r]

__device__ __forceinline__ float gelu_f(float v) {
    return 0.5f * v * (1.0f + erff(v * 0.70710678118654752440f));
}
__device__ __forceinline__ float gelu_fast(float v) {
    float u = 0.7978845608f * (v + 0.044715f * v * v * v);
    float th;
    asm("tanh.approx.f32 %0, %1;" : "=f"(th) : "f"(u));
    return 0.5f * v * (1.0f + th);
}
__device__ __forceinline__ uint32_t f2tf(float f) {
    uint32_t r; asm("cvt.rna.tf32.f32 %0, %1;" : "=r"(r) : "f"(f)); return r;
}
__device__ __forceinline__ void mma_tf32(float* c, const uint32_t* a, uint32_t b0, uint32_t b1) {
    asm volatile(
        "mma.sync.aligned.m16n8k8.row.col.f32.tf32.tf32.f32 "
        "{%0,%1,%2,%3}, {%4,%5,%6,%7}, {%8,%9}, {%0,%1,%2,%3};"
        : "+f"(c[0]), "+f"(c[1]), "+f"(c[2]), "+f"(c[3])
        : "r"(a[0]), "r"(a[1]), "r"(a[2]), "r"(a[3]), "r"(b0), "r"(b1));
}

// ---------------------------------------------------------------------------
// Kernel 1 (fused): blocks [0,512): conv stencil (2 planes/block, 4 warps per
//   plane, rolling-register rows, shfl halos).  blocks [512,640): PW2.
// ---------------------------------------------------------------------------
__global__ __launch_bounds__(256) void conv_pw2_kernel(
    const float* __restrict__ x, const float* __restrict__ exp_w2,
    const float* __restrict__ proj_w) {
    if (blockIdx.x >= 512) {
        int bi = blockIdx.x - 512;
        int e = bi >> 5;
        int d = ((bi & 31) << 2) + (threadIdx.x >> 6);
        int r = threadIdx.x & 63;
        const float* pw = proj_w + d * NC;
        const float* w2 = exp_w2 + (size_t)e * NC * NR + r;
        float a = 0.f;
        #pragma unroll 8
        for (int c = 0; c < NC; ++c) a += pw[c] * w2[c * NR];
        g_PW2[(e * NC + d) * NR + r] = a;
        return;
    }

    const int t = threadIdx.x;
    const int wid = t >> 5, lane = t & 31;
    const int plane = blockIdx.x * 2 + (wid >> 2);
    const int w4 = wid & 3;
    const float* p = x + (size_t)plane * NHW + lane * 4;
    const int r0 = w4 * 32;

    const float4 z = make_float4(0.f, 0.f, 0.f, 0.f);
    float4 prev = (r0 > 0) ? *(const float4*)(p + (r0 - 1) * 128) : z;
    float4 cur  = *(const float4*)(p + r0 * 128);
    float4 nxt  = *(const float4*)(p + (r0 + 1) * 128);
    float4 nxt2 = *(const float4*)(p + (r0 + 2) * 128);   // r0+2 <= 98, always valid

    float sumg = 0.f, sumx = 0.f;
    #pragma unroll 4
    for (int i = 0; i < 32; ++i) {
        int r = r0 + i;
        int rn = r + 3;
        float4 inc = (rn < 128) ? *(const float4*)(p + rn * 128) : z;

        sumx += cur.x + cur.y + cur.z + cur.w;

        float pl = __shfl_up_sync(0xffffffffu, prev.w, 1);
        float cl = __shfl_up_sync(0xffffffffu, cur.w, 1);
        float nl = __shfl_up_sync(0xffffffffu, nxt.w, 1);
        float pr = __shfl_down_sync(0xffffffffu, prev.x, 1);
        float cr = __shfl_down_sync(0xffffffffu, cur.x, 1);
        float nr = __shfl_down_sync(0xffffffffu, nxt.x, 1);
        if (lane == 0)  { pl = 0.f; cl = 0.f; nl = 0.f; }
        if (lane == 31) { pr = 0.f; cr = 0.f; nr = 0.f; }

        float nb0 = pl + prev.x + prev.y + cl + cur.y + nl + nxt.x + nxt.y;
        float nb1 = prev.x + prev.y + prev.z + cur.x + cur.z + nxt.x + nxt.y + nxt.z;
        float nb2 = prev.y + prev.z + prev.w + cur.y + cur.w + nxt.y + nxt.z + nxt.w;
        float nb3 = prev.z + prev.w + pr + cur.z + cr + nxt.z + nxt.w + nr;

        sumg += gelu_fast(8.f * cur.x - nb0);
        sumg += gelu_fast(8.f * cur.y - nb1);
        sumg += gelu_fast(8.f * cur.z - nb2);
        sumg += gelu_fast(8.f * cur.w - nb3);

        prev = cur; cur = nxt; nxt = nxt2; nxt2 = inc;
    }

    // warp reduce, then cross-warp per plane
    for (int o = 16; o > 0; o >>= 1) {
        sumg += __shfl_down_sync(0xffffffffu, sumg, o);
        sumx += __shfl_down_sync(0xffffffffu, sumx, o);
    }
    __shared__ float rg[8], rx[8];
    if (lane == 0) { rg[wid] = sumg; rx[wid] = sumx; }
    __syncthreads();
    if (t < 2) {
        float ag = 0.f, ax = 0.f;
        #pragma unroll
        for (int i = 0; i < 4; ++i) { ag += rg[t * 4 + i]; ax += rx[t * 4 + i]; }
        const float inv = 1.0f / 16384.0f;
        int pl = blockIdx.x * 2 + t;
        g_fe0[pl]    = ag * inv;
        g_pooled[pl] = ax * inv;
    }
}

// ---------------------------------------------------------------------------
// Kernel 2: routing, one block per batch
// ---------------------------------------------------------------------------
__global__ __launch_bounds__(256) void routing_kernel(
    const float* __restrict__ mlp_w1, const float* __restrict__ mlp_b1,
    const float* __restrict__ mlp_w2, const float* __restrict__ mlp_b2,
    const float* __restrict__ gate_w, const float* __restrict__ fgate_w) {
    __shared__ float s_in[NC], s_pool[NC], s_h1[256], s_fe[NC], s_log[NE];
    const int b = blockIdx.x;
    const int t = threadIdx.x;

    if (t < NC) { s_in[t] = g_fe0[b * NC + t]; s_pool[t] = g_pooled[b * NC + t]; }
    __syncthreads();
    {
        float a = mlp_b1[t];
        #pragma unroll 8
        for (int c = 0; c < NC; ++c) a += s_in[c] * mlp_w1[c * 256 + t];
        s_h1[t] = gelu_f(a);
    }
    __syncthreads();
    if (t < NC) {
        float a = mlp_b2[t];
        #pragma unroll 8
        for (int c = 0; c < 256; ++c) a += s_h1[c] * mlp_w2[c * NC + t];
        s_fe[t] = a;
    }
    __syncthreads();
    if (t < NE) {
        float a = 0.f;
        for (int c = 0; c < NC; ++c)
            a += s_pool[c] * gate_w[c * NE + t] + s_fe[c] * fgate_w[c * NE + t];
        s_log[t] = a;
    }
    __syncthreads();
    if (t == 0) {
        float sc[NE];
        float m = -1e30f;
        #pragma unroll
        for (int e = 0; e < NE; ++e) { sc[e] = s_log[e]; m = fmaxf(m, sc[e]); }
        float ss = 0.f;
        #pragma unroll
        for (int e = 0; e < NE; ++e) { sc[e] = expf(sc[e] - m); ss += sc[e]; }
        float inv = 1.0f / ss;
        #pragma unroll
        for (int e = 0; e < NE; ++e) sc[e] *= inv;
        int i0 = 0;
        #pragma unroll
        for (int e = 1; e < NE; ++e) if (sc[e] > sc[i0]) i0 = e;
        int i1 = -1;
        #pragma unroll
        for (int e = 0; e < NE; ++e) {
            if (e == i0) continue;
            if (i1 < 0 || sc[e] > sc[i1]) i1 = e;
        }
        g_sel[b * 2] = i0;  g_sel[b * 2 + 1] = i1;
        g_gate[b * 2] = sc[i0]; g_gate[b * 2 + 1] = sc[i1];
        g_gsum[b] = sc[i0] + sc[i1];
    }
}

// ---------------------------------------------------------------------------
// Main tensor-core kernel (mma.sync tf32), fragment-packed smem layouts.
//
// A (weights) layout: word = m*LDA + kmap(k),
//   kmap(k) = (k>>3)*8 + ((k>>2)&1) + (((k&3)<<1) ^ (((k>>5)&3)<<1))
//   -> per k-step, lane's (a0,a2)/(a1,a3) are adjacent pairs: LDS.64.
// B (acts) layout: word = k*LDB + (((n&7)*16) ^ (((n>>2)&1)<<4)) + (n>>3)
//   -> per k-step, lane's b-values for 4 n-blocks are contiguous: LDS.128.
// Both load and store patterns are bank-conflict-free by construction.
// ---------------------------------------------------------------------------

// stage [128m][128k] weight tile (rows 0..63 from a, 64..127 from b2), scaled
__device__ __forceinline__ void stage_w_cat(uint32_t* sW, const float* __restrict__ a,
                                            const float* __restrict__ b2, float sc, int t) {
    const int q = t & 31, w = t >> 5;
    const int swz = ((q >> 3) & 3) << 1;
    const int ob = (q >> 1) * 8 + (q & 1);
    const int o0 = ob + (0 ^ swz), o1 = ob + (2 ^ swz), o2 = ob + (4 ^ swz), o3 = ob + (6 ^ swz);
    #pragma unroll
    for (int i = 0; i < 16; ++i) {
        int row = w + 8 * i;
        const float* src = (i < 8) ? (a + row * 128) : (b2 + (row - 64) * 128);
        float4 u = *(const float4*)(src + q * 4);
        uint32_t* d = sW + row * LDA;
        d[o0] = f2tf(u.x * sc); d[o1] = f2tf(u.y * sc);
        d[o2] = f2tf(u.z * sc); d[o3] = f2tf(u.w * sc);
    }
}

// stage Mcat[d][k]: k<64 -> ga0*PW2[e0][d][k] ; k>=64 -> ga1*PW2[e1][d][k-64]
__device__ __forceinline__ void stage_mcat(uint32_t* sW, const float* __restrict__ pw2,
                                           int e0, int e1, float ga0, float ga1, int t) {
    const int q = t & 31, w = t >> 5;
    const int swz = ((q >> 3) & 3) << 1;
    const int ob = (q >> 1) * 8 + (q & 1);
    const int o0 = ob + (0 ^ swz), o1 = ob + (2 ^ swz), o2 = ob + (4 ^ swz), o3 = ob + (6 ^ swz);
    const float sc = (q < 16) ? ga0 : ga1;
    const float* base = pw2 + (size_t)((q < 16) ? e0 : e1) * NC * NR + (q & 15) * 4;
    #pragma unroll
    for (int i = 0; i < 16; ++i) {
        int d = w + 8 * i;
        float4 u = *(const float4*)(base + d * NR);
        uint32_t* dst = sW + d * LDA;
        dst[o0] = f2tf(u.x * sc); dst[o1] = f2tf(u.y * sc);
        dst[o2] = f2tf(u.z * sc); dst[o3] = f2tf(u.w * sc);
    }
}

// stage [128k][128n] activation tile (k = channel, n = pixel)
__device__ __forceinline__ void stage_act(uint32_t* sB, const float* __restrict__ gsrc, int t) {
    const int q = t & 31, w = t >> 5;
    const int qe = q & 1;
    const int nb = q >> 1;
    const int base0 = ((4 * qe + 0) * 16 ^ (qe << 4)) + nb;
    const int base1 = ((4 * qe + 1) * 16 ^ (qe << 4)) + nb;
    const int base2 = ((4 * qe + 2) * 16 ^ (qe << 4)) + nb;
    const int base3 = ((4 * qe + 3) * 16 ^ (qe << 4)) + nb;
    #pragma unroll
    for (int i = 0; i < 16; ++i) {
        int c = w + 8 * i;
        float4 u = *(const float4*)(gsrc + (size_t)c * NHW + q * 4);
        uint32_t* d = sB + c * LDB;
        d[base0] = f2tf(u.x); d[base1] = f2tf(u.y);
        d[base2] = f2tf(u.z); d[base3] = f2tf(u.w);
    }
}

// acc[mf][nf][4] += W[m0.., k] * B[k, n0..]   (M=32, N=64, K=128)
__device__ __forceinline__ void gemm_mma(const uint32_t* __restrict__ sW,
                                         const uint32_t* __restrict__ sB,
                                         float acc[2][8][4], int m0, int n0, int lane) {
    const int ar = lane >> 2, ac = lane & 3;
    const int nbase = n0 >> 3;
    const uint32_t boff = (uint32_t)((ar * 16) ^ (((ar >> 2) & 1) << 4)) + nbase;
    #pragma unroll
    for (int kk = 0; kk < 16; ++kk) {
        const int poff = kk * 8 + ((ac << 1) ^ ((kk >> 2) << 1));
        uint32_t a[2][4];
        #pragma unroll
        for (int mf = 0; mf < 2; ++mf) {
            const int row = m0 + mf * 16 + ar;
            uint2 p0 = *(const uint2*)(sW + row * LDA + poff);
            uint2 p1 = *(const uint2*)(sW + (row + 8) * LDA + poff);
            a[mf][0] = p0.x; a[mf][2] = p0.y;
            a[mf][1] = p1.x; a[mf][3] = p1.y;
        }
        const uint32_t r0 = (kk * 8 + ac) * LDB + boff;
        uint4 b00 = *(const uint4*)(sB + r0);
        uint4 b01 = *(const uint4*)(sB + r0 + 4);
        uint4 b10 = *(const uint4*)(sB + r0 + 4 * LDB);
        uint4 b11 = *(const uint4*)(sB + r0 + 4 * LDB + 4);
        mma_tf32(acc[0][0], a[0], b00.x, b10.x);  mma_tf32(acc[1][0], a[1], b00.x, b10.x);
        mma_tf32(acc[0][1], a[0], b00.y, b10.y);  mma_tf32(acc[1][1], a[1], b00.y, b10.y);
        mma_tf32(acc[0][2], a[0], b00.z, b10.z);  mma_tf32(acc[1][2], a[1], b00.z, b10.z);
        mma_tf32(acc[0][3], a[0], b00.w, b10.w);  mma_tf32(acc[1][3], a[1], b00.w, b10.w);
        mma_tf32(acc[0][4], a[0], b01.x, b11.x);  mma_tf32(acc[1][4], a[1], b01.x, b11.x);
        mma_tf32(acc[0][5], a[0], b01.y, b11.y);  mma_tf32(acc[1][5], a[1], b01.y, b11.y);
        mma_tf32(acc[0][6], a[0], b01.z, b11.z);  mma_tf32(acc[1][6], a[1], b01.z, b11.z);
        mma_tf32(acc[0][7], a[0], b01.w, b11.w);  mma_tf32(acc[1][7], a[1], b01.w, b11.w);
    }
}

__global__ __launch_bounds__(256, 1) void main_mma_kernel(
    const float* __restrict__ x, const float* __restrict__ sh,
    const float* __restrict__ exp_w0, const float* __restrict__ exp_w1,
    const float* __restrict__ proj_w, float* __restrict__ out) {
    extern __shared__ uint32_t smem[];
    uint32_t* sX = smem + SM_X;
    uint32_t* sS = smem + SM_S;     // later reused for T
    uint32_t* sW = smem + SM_W;

    const int t = threadIdx.x;
    const int lane = t & 31;
    const int wid = t >> 5;
    const int m0 = (wid >> 1) << 5;          // 0,32,64,96
    const int n0 = (wid & 1) << 6;           // 0,64
    const int b = blockIdx.y;
    const int hw0 = blockIdx.x * 128;

    const int   e0  = g_sel[b * 2],  e1  = g_sel[b * 2 + 1];
    const float ga0 = g_gate[b * 2], ga1 = g_gate[b * 2 + 1];
    const float gs  = g_gsum[b];

    const float* xb = x  + (size_t)b * NC * NHW + hw0;
    const float* sb = sh + (size_t)b * NC * NHW + hw0;

    // phase 0: stage X, S, Wcat0
    stage_act(sX, xb, t);
    stage_act(sS, sb, t);
    stage_w_cat(sW, exp_w0 + (size_t)e0 * NR * NC, exp_w0 + (size_t)e1 * NR * NC, 1.f, t);
    __syncthreads();

    // GEMM1: accA = Wcat0 @ X
    float accA[2][8][4];
    #pragma unroll
    for (int i = 0; i < 2; ++i)
        #pragma unroll
        for (int j = 0; j < 8; ++j)
            #pragma unroll
            for (int kq = 0; kq < 4; ++kq) accA[i][j][kq] = 0.f;
    gemm_mma(sW, sX, accA, m0, n0, lane);
    __syncthreads();

    // phase 1: stage Wcat1
    stage_w_cat(sW, exp_w1 + (size_t)e0 * NR * NC, exp_w1 + (size_t)e1 * NR * NC, 1.f, t);
    __syncthreads();

    // GEMM2: accG = Wcat1 @ Sh
    float accG[2][8][4];
    #pragma unroll
    for (int i = 0; i < 2; ++i)
        #pragma unroll
        for (int j = 0; j < 8; ++j)
            #pragma unroll
            for (int kq = 0; kq < 4; ++kq) accG[i][j][kq] = 0.f;
    gemm_mma(sW, sS, accG, m0, n0, lane);
    __syncthreads();           // done reading sS and sW

    // T = accA * silu(accG) -> sS (B layout, k=rank); Mcat -> sW
    {
        const int ar = lane >> 2, ac = lane & 3;
        #pragma unroll
        for (int mf = 0; mf < 2; ++mf) {
            #pragma unroll
            for (int nf = 0; nf < 8; ++nf) {
                const int nlo0 = 2 * ac, nlo1 = 2 * ac + 1;
                const int off0 = ((nlo0 * 16) ^ (((nlo0 >> 2) & 1) << 4)) + (n0 >> 3) + nf;
                const int off1 = ((nlo1 * 16) ^ (((nlo1 >> 2) & 1) << 4)) + (n0 >> 3) + nf;
                #pragma unroll
                for (int half = 0; half < 2; ++half) {
                    const int row = m0 + mf * 16 + ar + half * 8;
                    float a0 = accA[mf][nf][half * 2 + 0];
                    float a1 = accA[mf][nf][half * 2 + 1];
                    float g0 = accG[mf][nf][half * 2 + 0];
                    float g1 = accG[mf][nf][half * 2 + 1];
                    sS[row * LDB + off0] = f2tf(a0 * (g0 / (1.f + __expf(-g0))));
                    sS[row * LDB + off1] = f2tf(a1 * (g1 / (1.f + __expf(-g1))));
                }
            }
        }
    }
    stage_mcat(sW, g_PW2, e0, e1, ga0, ga1, t);
    __syncthreads();

    // GEMM3: accO = Mcat @ T
    float accO[2][8][4];
    #pragma unroll
    for (int i = 0; i < 2; ++i)
        #pragma unroll
        for (int j = 0; j < 8; ++j)
            #pragma unroll
            for (int kq = 0; kq < 4; ++kq) accO[i][j][kq] = 0.f;
    gemm_mma(sW, sS, accO, m0, n0, lane);
    __syncthreads();

    // phase 3: stage gs*proj
    stage_w_cat(sW, proj_w, proj_w + 64 * NC, gs, t);
    __syncthreads();

    // GEMM4: accO += (gs*proj) @ X
    gemm_mma(sW, sX, accO, m0, n0, lane);

    // epilogue
    {
        const int ar = lane >> 2, ac = lane & 3;
        float* ob = out + (size_t)b * NC * NHW + hw0;
        #pragma unroll
        for (int mf = 0; mf < 2; ++mf) {
            #pragma unroll
            for (int nf = 0; nf < 8; ++nf) {
                const int col = n0 + nf * 8 + 2 * ac;
                #pragma unroll
                for (int half = 0; half < 2; ++half) {
                    const int row = m0 + mf * 16 + ar + half * 8;
                    float2 v = make_float2(accO[mf][nf][half * 2 + 0],
                                           accO[mf][nf][half * 2 + 1]);
                    *(float2*)(ob + (size_t)row * NHW + col) = v;
                }
            }
        }
    }
}

// ---------------------------------------------------------------------------
extern "C" void kernel_launch(void* const* d_in, const int* in_sizes, int n_in,
                              void* d_out, int out_size) {
    const float* x       = (const float*)d_in[0];
    const float* sh      = (const float*)d_in[1];
    const float* mlp_w1  = (const float*)d_in[2];
    const float* mlp_b1  = (const float*)d_in[3];
    const float* mlp_w2  = (const float*)d_in[4];
    const float* mlp_b2  = (const float*)d_in[5];
    const float* gate_w  = (const float*)d_in[6];
    const float* fgate_w = (const float*)d_in[7];
    const float* exp_w0  = (const float*)d_in[8];
    const float* exp_w1  = (const float*)d_in[9];
    const float* exp_w2  = (const float*)d_in[10];
    const float* proj_w  = (const float*)d_in[11];
    float* out = (float*)d_out;

    cudaFuncSetAttribute(main_mma_kernel, cudaFuncAttributeMaxDynamicSharedMemorySize, SMEM_MAIN);

    conv_pw2_kernel<<<640, 256>>>(x, exp_w2, proj_w);
    routing_kernel<<<NB, 256>>>(mlp_w1, mlp_b1, mlp_w2, mlp_b2, gate_w, fgate_w);
    main_mma_kernel<<<dim3(NHW / 128, NB), 256, SMEM_MAIN>>>(x, sh, exp_w0, exp_w1, proj_w, out);
}

// round 10
// speedup vs baseline: 1.4170x; 1.4170x over previous
#include <cuda_runtime.h>
#include <math.h>
#include <stdint.h>

// Problem constants
#define NB 8
#define NC 128
#define NHW 16384
#define NE 4
#define NR 64

// smem layout (words) for main kernel — R3 proven layout
#define LDW 132           // weight tile ld  (conflict-free A-frag LDS)
#define LDX 136           // act tile ld     (conflict-free B-frag LDS)
#define SM_X 0
#define SM_S (128 * LDX)
#define SM_W (2 * 128 * LDX)
#define SMEM_MAIN ((2 * 128 * LDX + 128 * LDW) * 4)   // 206848 bytes

// ---------------- device scratch ----------------
__device__ float g_fe0[NB * NC];
__device__ float g_pooled[NB * NC];
__device__ int   g_sel[NB * 2];
__device__ float g_gate[NB * 2];
__device__ float g_gsum[NB];
__device__ float g_PW2[NE * NC * NR];   // proj_w @ exp_w2[e] : [e][d][r]

__device__ __forceinline__ float gelu_f(float v) {
    return 0.5f * v * (1.0f + erff(v * 0.70710678118654752440f));
}
__device__ __forceinline__ float gelu_fast(float v) {
    float u = 0.7978845608f * (v + 0.044715f * v * v * v);
    float th;
    asm("tanh.approx.f32 %0, %1;" : "=f"(th) : "f"(u));
    return 0.5f * v * (1.0f + th);
}
__device__ __forceinline__ uint32_t f2tf(float f) {
    uint32_t r; asm("cvt.rna.tf32.f32 %0, %1;" : "=r"(r) : "f"(f)); return r;
}
__device__ __forceinline__ void mma_tf32(float* c, const uint32_t* a, const uint32_t* b) {
    asm volatile(
        "mma.sync.aligned.m16n8k8.row.col.f32.tf32.tf32.f32 "
        "{%0,%1,%2,%3}, {%4,%5,%6,%7}, {%8,%9}, {%0,%1,%2,%3};"
        : "+f"(c[0]), "+f"(c[1]), "+f"(c[2]), "+f"(c[3])
        : "r"(a[0]), "r"(a[1]), "r"(a[2]), "r"(a[3]), "r"(b[0]), "r"(b[1]));
}

// ---------------------------------------------------------------------------
// Kernel 1 (fused): blocks [0,512): conv stencil (2 planes/block, 4 warps per
//   plane, rolling-register rows, shfl halos).  blocks [512,640): PW2.
// ---------------------------------------------------------------------------
__global__ __launch_bounds__(256) void conv_pw2_kernel(
    const float* __restrict__ x, const float* __restrict__ exp_w2,
    const float* __restrict__ proj_w) {
    if (blockIdx.x >= 512) {
        int bi = blockIdx.x - 512;
        int e = bi >> 5;
        int d = ((bi & 31) << 2) + (threadIdx.x >> 6);
        int r = threadIdx.x & 63;
        const float* pw = proj_w + d * NC;
        const float* w2 = exp_w2 + (size_t)e * NC * NR + r;
        float a = 0.f;
        #pragma unroll 8
        for (int c = 0; c < NC; ++c) a += pw[c] * w2[c * NR];
        g_PW2[(e * NC + d) * NR + r] = a;
        return;
    }

    const int t = threadIdx.x;
    const int wid = t >> 5, lane = t & 31;
    const int plane = blockIdx.x * 2 + (wid >> 2);
    const int w4 = wid & 3;
    const float* p = x + (size_t)plane * NHW + lane * 4;
    const int r0 = w4 * 32;

    const float4 z = make_float4(0.f, 0.f, 0.f, 0.f);
    float4 prev = (r0 > 0) ? *(const float4*)(p + (r0 - 1) * 128) : z;
    float4 cur  = *(const float4*)(p + r0 * 128);
    float4 nxt  = *(const float4*)(p + (r0 + 1) * 128);
    float4 nxt2 = *(const float4*)(p + (r0 + 2) * 128);

    float sumg = 0.f, sumx = 0.f;
    #pragma unroll 4
    for (int i = 0; i < 32; ++i) {
        int rn = r0 + i + 3;
        float4 inc = (rn < 128) ? *(const float4*)(p + rn * 128) : z;

        sumx += cur.x + cur.y + cur.z + cur.w;

        float pl = __shfl_up_sync(0xffffffffu, prev.w, 1);
        float cl = __shfl_up_sync(0xffffffffu, cur.w, 1);
        float nl = __shfl_up_sync(0xffffffffu, nxt.w, 1);
        float pr = __shfl_down_sync(0xffffffffu, prev.x, 1);
        float cr = __shfl_down_sync(0xffffffffu, cur.x, 1);
        float nr = __shfl_down_sync(0xffffffffu, nxt.x, 1);
        if (lane == 0)  { pl = 0.f; cl = 0.f; nl = 0.f; }
        if (lane == 31) { pr = 0.f; cr = 0.f; nr = 0.f; }

        float nb0 = pl + prev.x + prev.y + cl + cur.y + nl + nxt.x + nxt.y;
        float nb1 = prev.x + prev.y + prev.z + cur.x + cur.z + nxt.x + nxt.y + nxt.z;
        float nb2 = prev.y + prev.z + prev.w + cur.y + cur.w + nxt.y + nxt.z + nxt.w;
        float nb3 = prev.z + prev.w + pr + cur.z + cr + nxt.z + nxt.w + nr;

        sumg += gelu_fast(8.f * cur.x - nb0);
        sumg += gelu_fast(8.f * cur.y - nb1);
        sumg += gelu_fast(8.f * cur.z - nb2);
        sumg += gelu_fast(8.f * cur.w - nb3);

        prev = cur; cur = nxt; nxt = nxt2; nxt2 = inc;
    }

    for (int o = 16; o > 0; o >>= 1) {
        sumg += __shfl_down_sync(0xffffffffu, sumg, o);
        sumx += __shfl_down_sync(0xffffffffu, sumx, o);
    }
    __shared__ float rg[8], rx[8];
    if (lane == 0) { rg[wid] = sumg; rx[wid] = sumx; }
    __syncthreads();
    if (t < 2) {
        float ag = 0.f, ax = 0.f;
        #pragma unroll
        for (int i = 0; i < 4; ++i) { ag += rg[t * 4 + i]; ax += rx[t * 4 + i]; }
        const float inv = 1.0f / 16384.0f;
        int pl = blockIdx.x * 2 + t;
        g_fe0[pl]    = ag * inv;
        g_pooled[pl] = ax * inv;
    }
}

// ---------------------------------------------------------------------------
// Kernel 2: routing, one block per batch
// ---------------------------------------------------------------------------
__global__ __launch_bounds__(256) void routing_kernel(
    const float* __restrict__ mlp_w1, const float* __restrict__ mlp_b1,
    const float* __restrict__ mlp_w2, const float* __restrict__ mlp_b2,
    const float* __restrict__ gate_w, const float* __restrict__ fgate_w) {
    __shared__ float s_in[NC], s_pool[NC], s_h1[256], s_fe[NC], s_log[NE];
    const int b = blockIdx.x;
    const int t = threadIdx.x;

    if (t < NC) { s_in[t] = g_fe0[b * NC + t]; s_pool[t] = g_pooled[b * NC + t]; }
    __syncthreads();
    {
        float a = mlp_b1[t];
        #pragma unroll 8
        for (int c = 0; c < NC; ++c) a += s_in[c] * mlp_w1[c * 256 + t];
        s_h1[t] = gelu_f(a);
    }
    __syncthreads();
    if (t < NC) {
        float a = mlp_b2[t];
        #pragma unroll 8
        for (int c = 0; c < 256; ++c) a += s_h1[c] * mlp_w2[c * NC + t];
        s_fe[t] = a;
    }
    __syncthreads();
    if (t < NE) {
        float a = 0.f;
        for (int c = 0; c < NC; ++c)
            a += s_pool[c] * gate_w[c * NE + t] + s_fe[c] * fgate_w[c * NE + t];
        s_log[t] = a;
    }
    __syncthreads();
    if (t == 0) {
        float sc[NE];
        float m = -1e30f;
        #pragma unroll
        for (int e = 0; e < NE; ++e) { sc[e] = s_log[e]; m = fmaxf(m, sc[e]); }
        float ss = 0.f;
        #pragma unroll
        for (int e = 0; e < NE; ++e) { sc[e] = expf(sc[e] - m); ss += sc[e]; }
        float inv = 1.0f / ss;
        #pragma unroll
        for (int e = 0; e < NE; ++e) sc[e] *= inv;
        int i0 = 0;
        #pragma unroll
        for (int e = 1; e < NE; ++e) if (sc[e] > sc[i0]) i0 = e;
        int i1 = -1;
        #pragma unroll
        for (int e = 0; e < NE; ++e) {
            if (e == i0) continue;
            if (i1 < 0 || sc[e] > sc[i1]) i1 = e;
        }
        g_sel[b * 2] = i0;  g_sel[b * 2 + 1] = i1;
        g_gate[b * 2] = sc[i0]; g_gate[b * 2 + 1] = sc[i1];
        g_gsum[b] = sc[i0] + sc[i1];
    }
}

// ---------------------------------------------------------------------------
// Main tensor-core kernel (mma.sync tf32) — R3-proven layout, no prefetch.
// ---------------------------------------------------------------------------

__device__ __forceinline__ void stage_w_cat(uint32_t* sW, const float* __restrict__ a,
                                            const float* __restrict__ b2, float sc, int t) {
    #pragma unroll
    for (int f = t; f < 4096; f += 256) {
        int row = f >> 5, q = f & 31;
        const float* src = (row < 64) ? (a + row * 128 + q * 4)
                                      : (b2 + (row - 64) * 128 + q * 4);
        float4 u = *(const float4*)src;
        uint4 w;
        w.x = f2tf(u.x * sc); w.y = f2tf(u.y * sc);
        w.z = f2tf(u.z * sc); w.w = f2tf(u.w * sc);
        *(uint4*)(sW + row * LDW + q * 4) = w;
    }
}

__device__ __forceinline__ void stage_mcat(uint32_t* sW, const float* __restrict__ pw2,
                                           int e0, int e1, float ga0, float ga1, int t) {
    #pragma unroll
    for (int f = t; f < 4096; f += 256) {
        int row = f >> 5, q = f & 31;
        int lo = (q < 16);
        const float* src = pw2 + ((size_t)(lo ? e0 : e1) * NC + row) * NR + (q & 15) * 4;
        float sc = lo ? ga0 : ga1;
        float4 u = *(const float4*)src;
        uint4 w;
        w.x = f2tf(u.x * sc); w.y = f2tf(u.y * sc);
        w.z = f2tf(u.z * sc); w.w = f2tf(u.w * sc);
        *(uint4*)(sW + row * LDW + q * 4) = w;
    }
}

__device__ __forceinline__ void stage_act(uint32_t* sA, const float* __restrict__ gsrc, int t) {
    #pragma unroll
    for (int f = t; f < 4096; f += 256) {
        int c = f >> 5, q = f & 31;
        float4 u = *(const float4*)(gsrc + (size_t)c * NHW + q * 4);
        uint4 w;
        w.x = f2tf(u.x); w.y = f2tf(u.y); w.z = f2tf(u.z); w.w = f2tf(u.w);
        *(uint4*)(sA + c * LDX + q * 4) = w;
    }
}

__device__ __forceinline__ void gemm_mma(const uint32_t* __restrict__ sW,
                                         const uint32_t* __restrict__ sB,
                                         float acc[2][8][4], int m0, int n0, int lane) {
    const int ar = lane >> 2, ac = lane & 3;
    #pragma unroll
    for (int kk = 0; kk < 16; ++kk) {
        const int k0 = kk << 3;
        uint32_t a[2][4];
        #pragma unroll
        for (int mf = 0; mf < 2; ++mf) {
            const uint32_t* pa = sW + (m0 + mf * 16 + ar) * LDW + k0 + ac;
            a[mf][0] = pa[0];
            a[mf][2] = pa[4];
            a[mf][1] = pa[8 * LDW];
            a[mf][3] = pa[8 * LDW + 4];
        }
        #pragma unroll
        for (int nf = 0; nf < 8; ++nf) {
            const uint32_t* pb = sB + (k0 + ac) * LDX + n0 + nf * 8 + ar;
            uint32_t b[2];
            b[0] = pb[0];
            b[1] = pb[4 * LDX];
            mma_tf32(acc[0][nf], a[0], b);
            mma_tf32(acc[1][nf], a[1], b);
        }
    }
}

__global__ __launch_bounds__(256, 1) void main_mma_kernel(
    const float* __restrict__ x, const float* __restrict__ sh,
    const float* __restrict__ exp_w0, const float* __restrict__ exp_w1,
    const float* __restrict__ proj_w, float* __restrict__ out) {
    extern __shared__ uint32_t smem[];
    uint32_t* sX = smem + SM_X;
    uint32_t* sS = smem + SM_S;     // later reused for T
    uint32_t* sW = smem + SM_W;

    const int t = threadIdx.x;
    const int lane = t & 31;
    const int wid = t >> 5;
    const int m0 = (wid >> 1) << 5;          // 0,32,64,96
    const int n0 = (wid & 1) << 6;           // 0,64
    const int b = blockIdx.y;
    const int hw0 = blockIdx.x * 128;

    const int   e0  = g_sel[b * 2],  e1  = g_sel[b * 2 + 1];
    const float ga0 = g_gate[b * 2], ga1 = g_gate[b * 2 + 1];
    const float gs  = g_gsum[b];

    const float* xb = x  + (size_t)b * NC * NHW + hw0;
    const float* sb = sh + (size_t)b * NC * NHW + hw0;

    // phase 0: stage x, shared, Wcat0
    stage_act(sX, xb, t);
    stage_act(sS, sb, t);
    stage_w_cat(sW, exp_w0 + (size_t)e0 * NR * NC, exp_w0 + (size_t)e1 * NR * NC, 1.f, t);
    __syncthreads();

    // GEMM1: accA = Wcat0 @ X
    float accA[2][8][4];
    #pragma unroll
    for (int i = 0; i < 2; ++i)
        #pragma unroll
        for (int j = 0; j < 8; ++j)
            #pragma unroll
            for (int kq = 0; kq < 4; ++kq) accA[i][j][kq] = 0.f;
    gemm_mma(sW, sX, accA, m0, n0, lane);
    __syncthreads();

    // phase 1: stage Wcat1
    stage_w_cat(sW, exp_w1 + (size_t)e0 * NR * NC, exp_w1 + (size_t)e1 * NR * NC, 1.f, t);
    __syncthreads();

    // GEMM2: accG = Wcat1 @ Sh
    float accG[2][8][4];
    #pragma unroll
    for (int i = 0; i < 2; ++i)
        #pragma unroll
        for (int j = 0; j < 8; ++j)
            #pragma unroll
            for (int kq = 0; kq < 4; ++kq) accG[i][j][kq] = 0.f;
    gemm_mma(sW, sS, accG, m0, n0, lane);
    __syncthreads();   // everyone done reading sS and sW

    // T = accA * silu(accG) -> sS (as tf32), row = rank, col = pixel
    {
        const int ar = lane >> 2, ac = lane & 3;
        #pragma unroll
        for (int mf = 0; mf < 2; ++mf) {
            #pragma unroll
            for (int nf = 0; nf < 8; ++nf) {
                const int col = n0 + nf * 8 + 2 * ac;
                #pragma unroll
                for (int half = 0; half < 2; ++half) {
                    const int row = m0 + mf * 16 + ar + half * 8;
                    float a0 = accA[mf][nf][half * 2 + 0];
                    float a1 = accA[mf][nf][half * 2 + 1];
                    float g0 = accG[mf][nf][half * 2 + 0];
                    float g1 = accG[mf][nf][half * 2 + 1];
                    uint2 w;
                    w.x = f2tf(a0 * (g0 / (1.f + __expf(-g0))));
                    w.y = f2tf(a1 * (g1 / (1.f + __expf(-g1))));
                    *(uint2*)(sS + row * LDX + col) = w;
                }
            }
        }
    }
    stage_mcat(sW, g_PW2, e0, e1, ga0, ga1, t);
    __syncthreads();

    // GEMM3: accO = Mcat @ T
    float accO[2][8][4];
    #pragma unroll
    for (int i = 0; i < 2; ++i)
        #pragma unroll
        for (int j = 0; j < 8; ++j)
            #pragma unroll
            for (int kq = 0; kq < 4; ++kq) accO[i][j][kq] = 0.f;
    gemm_mma(sW, sS, accO, m0, n0, lane);
    __syncthreads();

    // phase 3: stage gs*proj
    stage_w_cat(sW, proj_w, proj_w + 64 * NC, gs, t);
    __syncthreads();

    // GEMM4: accO += (gs*proj) @ X
    gemm_mma(sW, sX, accO, m0, n0, lane);

    // epilogue
    {
        const int ar = lane >> 2, ac = lane & 3;
        float* ob = out + (size_t)b * NC * NHW + hw0;
        #pragma unroll
        for (int mf = 0; mf < 2; ++mf) {
            #pragma unroll
            for (int nf = 0; nf < 8; ++nf) {
                const int col = n0 + nf * 8 + 2 * ac;
                #pragma unroll
                for (int half = 0; half < 2; ++half) {
                    const int row = m0 + mf * 16 + ar + half * 8;
                    float2 v = make_float2(accO[mf][nf][half * 2 + 0],
                                           accO[mf][nf][half * 2 + 1]);
                    *(float2*)(ob + (size_t)row * NHW + col) = v;
                }
            }
        }
    }
}

// ---------------------------------------------------------------------------
extern "C" void kernel_launch(void* const* d_in, const int* in_sizes, int n_in,
                              void* d_out, int out_size) {
    const float* x       = (const float*)d_in[0];
    const float* sh      = (const float*)d_in[1];
    const float* mlp_w1  = (const float*)d_in[2];
    const float* mlp_b1  = (const float*)d_in[3];
    const float* mlp_w2  = (const float*)d_in[4];
    const float* mlp_b2  = (const float*)d_in[5];
    const float* gate_w  = (const float*)d_in[6];
    const float* fgate_w = (const float*)d_in[7];
    const float* exp_w0  = (const float*)d_in[8];
    const float* exp_w1  = (const float*)d_in[9];
    const float* exp_w2  = (const float*)d_in[10];
    const float* proj_w  = (const float*)d_in[11];
    float* out = (float*)d_out;

    cudaFuncSetAttribute(main_mma_kernel, cudaFuncAttributeMaxDynamicSharedMemorySize, SMEM_MAIN);

    conv_pw2_kernel<<<640, 256>>>(x, exp_w2, proj_w);
    routing_kernel<<<NB, 256>>>(mlp_w1, mlp_b1, mlp_w2, mlp_b2, gate_w, fgate_w);
    main_mma_kernel<<<dim3(NHW / 128, NB), 256, SMEM_MAIN>>>(x, sh, exp_w0, exp_w1, proj_w, out);
}

// round 11
// speedup vs baseline: 1.4701x; 1.0375x over previous
#include <cuda_runtime.h>
#include <math.h>
#include <stdint.h>

// Problem constants
#define NB 8
#define NC 128
#define NHW 16384
#define NE 4
#define NR 64

// smem layout (words) for main kernel — R3 proven layout
#define LDW 132           // weight tile ld  (conflict-free A-frag LDS)
#define LDX 136           // act tile ld     (conflict-free B-frag LDS)
#define SM_X 0
#define SM_S (128 * LDX)
#define SM_W (2 * 128 * LDX)
#define SMEM_MAIN ((2 * 128 * LDX + 128 * LDW) * 4)   // 206848 bytes

// ---------------- device scratch ----------------
__device__ float g_fe0[NB * NC];
__device__ float g_pooled[NB * NC];
__device__ int   g_sel[NB * 2];
__device__ float g_gate[NB * 2];
__device__ float g_gsum[NB];
// pre-converted tf32 weight tiles (batch-independent)
__device__ __align__(16) uint32_t g_w0tf[NE * NR * NC];    // [e][r][c]
__device__ __align__(16) uint32_t g_w1tf[NE * NR * NC];    // [e][r][c]
__device__ __align__(16) uint32_t g_pw2tf[NE * NC * NR];   // [e][d][r], unscaled
__device__ __align__(16) uint32_t g_projtf[NC * NC];       // [d][c], unscaled

__device__ __forceinline__ float gelu_f(float v) {
    return 0.5f * v * (1.0f + erff(v * 0.70710678118654752440f));
}
__device__ __forceinline__ float gelu_fast(float v) {
    float u = 0.7978845608f * (v + 0.044715f * v * v * v);
    float th;
    asm("tanh.approx.f32 %0, %1;" : "=f"(th) : "f"(u));
    return 0.5f * v * (1.0f + th);
}
__device__ __forceinline__ uint32_t f2tf(float f) {
    uint32_t r; asm("cvt.rna.tf32.f32 %0, %1;" : "=r"(r) : "f"(f)); return r;
}
__device__ __forceinline__ void mma_tf32(float* c, const uint32_t* a, const uint32_t* b) {
    asm volatile(
        "mma.sync.aligned.m16n8k8.row.col.f32.tf32.tf32.f32 "
        "{%0,%1,%2,%3}, {%4,%5,%6,%7}, {%8,%9}, {%0,%1,%2,%3};"
        : "+f"(c[0]), "+f"(c[1]), "+f"(c[2]), "+f"(c[3])
        : "r"(a[0]), "r"(a[1]), "r"(a[2]), "r"(a[3]), "r"(b[0]), "r"(b[1]));
}
__device__ __forceinline__ void cp16(uint32_t saddr, const uint32_t* g) {
    asm volatile("{ .reg .u64 ga; cvta.to.global.u64 ga, %1; "
                 "cp.async.ca.shared.global [%0], [ga], 16; }"
                 :: "r"(saddr), "l"(g) : "memory");
}
#define CP_COMMIT() asm volatile("cp.async.commit_group;" ::: "memory")
#define CP_WAIT1()  asm volatile("cp.async.wait_group 1;" ::: "memory")
#define CP_WAIT0()  asm volatile("cp.async.wait_group 0;" ::: "memory")

// ---------------------------------------------------------------------------
// Kernel 1 (fused): [0,512) conv stencil; [512,640) PW2->tf32; [640,660)
//   linear tf32 conversion of exp_w0 / exp_w1 / proj_w.
// ---------------------------------------------------------------------------
__global__ __launch_bounds__(256) void conv_pw2_kernel(
    const float* __restrict__ x, const float* __restrict__ exp_w2,
    const float* __restrict__ proj_w, const float* __restrict__ exp_w0,
    const float* __restrict__ exp_w1) {
    const int t = threadIdx.x;
    if (blockIdx.x >= 640) {
        // ---- linear tf32 conversion, 4096 elems (1024 float4) per block ----
        int c = blockIdx.x - 640;
        const float* src;
        uint32_t* dst;
        if (c < 8)       { src = exp_w0 + c * 4096;        dst = g_w0tf + c * 4096; }
        else if (c < 16) { src = exp_w1 + (c - 8) * 4096;  dst = g_w1tf + (c - 8) * 4096; }
        else             { src = proj_w + (c - 16) * 4096; dst = g_projtf + (c - 16) * 4096; }
        #pragma unroll
        for (int i = 0; i < 4; ++i) {
            int f = t + (i << 8);
            float4 u = ((const float4*)src)[f];
            uint4 w;
            w.x = f2tf(u.x); w.y = f2tf(u.y); w.z = f2tf(u.z); w.w = f2tf(u.w);
            ((uint4*)dst)[f] = w;
        }
        return;
    }
    if (blockIdx.x >= 512) {
        // ---- PW2[e][d][r] = sum_c proj_w[d][c]*exp_w2[e][c][r], tf32 out ----
        int bi = blockIdx.x - 512;
        int e = bi >> 5;
        int d = ((bi & 31) << 2) + (t >> 6);
        int r = t & 63;
        const float* pw = proj_w + d * NC;
        const float* w2 = exp_w2 + (size_t)e * NC * NR + r;
        float a = 0.f;
        #pragma unroll 8
        for (int c = 0; c < NC; ++c) a += pw[c] * w2[c * NR];
        g_pw2tf[(e * NC + d) * NR + r] = f2tf(a);
        return;
    }

    // ---- conv stencil: 2 planes/block, rolling registers, shfl halos ----
    const int wid = t >> 5, lane = t & 31;
    const int plane = blockIdx.x * 2 + (wid >> 2);
    const int w4 = wid & 3;
    const float* p = x + (size_t)plane * NHW + lane * 4;
    const int r0 = w4 * 32;

    const float4 z = make_float4(0.f, 0.f, 0.f, 0.f);
    float4 prev = (r0 > 0) ? *(const float4*)(p + (r0 - 1) * 128) : z;
    float4 cur  = *(const float4*)(p + r0 * 128);
    float4 nxt  = *(const float4*)(p + (r0 + 1) * 128);
    float4 nxt2 = *(const float4*)(p + (r0 + 2) * 128);

    float sumg = 0.f, sumx = 0.f;
    #pragma unroll 4
    for (int i = 0; i < 32; ++i) {
        int rn = r0 + i + 3;
        float4 inc = (rn < 128) ? *(const float4*)(p + rn * 128) : z;

        sumx += cur.x + cur.y + cur.z + cur.w;

        float pl = __shfl_up_sync(0xffffffffu, prev.w, 1);
        float cl = __shfl_up_sync(0xffffffffu, cur.w, 1);
        float nl = __shfl_up_sync(0xffffffffu, nxt.w, 1);
        float pr = __shfl_down_sync(0xffffffffu, prev.x, 1);
        float cr = __shfl_down_sync(0xffffffffu, cur.x, 1);
        float nr = __shfl_down_sync(0xffffffffu, nxt.x, 1);
        if (lane == 0)  { pl = 0.f; cl = 0.f; nl = 0.f; }
        if (lane == 31) { pr = 0.f; cr = 0.f; nr = 0.f; }

        float nb0 = pl + prev.x + prev.y + cl + cur.y + nl + nxt.x + nxt.y;
        float nb1 = prev.x + prev.y + prev.z + cur.x + cur.z + nxt.x + nxt.y + nxt.z;
        float nb2 = prev.y + prev.z + prev.w + cur.y + cur.w + nxt.y + nxt.z + nxt.w;
        float nb3 = prev.z + prev.w + pr + cur.z + cr + nxt.z + nxt.w + nr;

        sumg += gelu_fast(8.f * cur.x - nb0);
        sumg += gelu_fast(8.f * cur.y - nb1);
        sumg += gelu_fast(8.f * cur.z - nb2);
        sumg += gelu_fast(8.f * cur.w - nb3);

        prev = cur; cur = nxt; nxt = nxt2; nxt2 = inc;
    }

    for (int o = 16; o > 0; o >>= 1) {
        sumg += __shfl_down_sync(0xffffffffu, sumg, o);
        sumx += __shfl_down_sync(0xffffffffu, sumx, o);
    }
    __shared__ float rg[8], rx[8];
    if (lane == 0) { rg[wid] = sumg; rx[wid] = sumx; }
    __syncthreads();
    if (t < 2) {
        float ag = 0.f, ax = 0.f;
        #pragma unroll
        for (int i = 0; i < 4; ++i) { ag += rg[t * 4 + i]; ax += rx[t * 4 + i]; }
        const float inv = 1.0f / 16384.0f;
        int pl = blockIdx.x * 2 + t;
        g_fe0[pl]    = ag * inv;
        g_pooled[pl] = ax * inv;
    }
}

// ---------------------------------------------------------------------------
// Kernel 2: routing, one block per batch
// ---------------------------------------------------------------------------
__global__ __launch_bounds__(256) void routing_kernel(
    const float* __restrict__ mlp_w1, const float* __restrict__ mlp_b1,
    const float* __restrict__ mlp_w2, const float* __restrict__ mlp_b2,
    const float* __restrict__ gate_w, const float* __restrict__ fgate_w) {
    __shared__ float s_in[NC], s_pool[NC], s_h1[256], s_fe[NC], s_log[NE];
    const int b = blockIdx.x;
    const int t = threadIdx.x;

    if (t < NC) { s_in[t] = g_fe0[b * NC + t]; s_pool[t] = g_pooled[b * NC + t]; }
    __syncthreads();
    {
        float a = mlp_b1[t];
        #pragma unroll 8
        for (int c = 0; c < NC; ++c) a += s_in[c] * mlp_w1[c * 256 + t];
        s_h1[t] = gelu_f(a);
    }
    __syncthreads();
    if (t < NC) {
        float a = mlp_b2[t];
        #pragma unroll 8
        for (int c = 0; c < 256; ++c) a += s_h1[c] * mlp_w2[c * NC + t];
        s_fe[t] = a;
    }
    __syncthreads();
    if (t < NE) {
        float a = 0.f;
        for (int c = 0; c < NC; ++c)
            a += s_pool[c] * gate_w[c * NE + t] + s_fe[c] * fgate_w[c * NE + t];
        s_log[t] = a;
    }
    __syncthreads();
    if (t == 0) {
        float sc[NE];
        float m = -1e30f;
        #pragma unroll
        for (int e = 0; e < NE; ++e) { sc[e] = s_log[e]; m = fmaxf(m, sc[e]); }
        float ss = 0.f;
        #pragma unroll
        for (int e = 0; e < NE; ++e) { sc[e] = expf(sc[e] - m); ss += sc[e]; }
        float inv = 1.0f / ss;
        #pragma unroll
        for (int e = 0; e < NE; ++e) sc[e] *= inv;
        int i0 = 0;
        #pragma unroll
        for (int e = 1; e < NE; ++e) if (sc[e] > sc[i0]) i0 = e;
        int i1 = -1;
        #pragma unroll
        for (int e = 0; e < NE; ++e) {
            if (e == i0) continue;
            if (i1 < 0 || sc[e] > sc[i1]) i1 = e;
        }
        g_sel[b * 2] = i0;  g_sel[b * 2 + 1] = i1;
        g_gate[b * 2] = sc[i0]; g_gate[b * 2 + 1] = sc[i1];
        g_gsum[b] = sc[i0] + sc[i1];
    }
}

// ---------------------------------------------------------------------------
// Main tensor-core kernel — cp.async K-half double-buffered weight staging.
// ---------------------------------------------------------------------------

// fill half 'h' of sW from a 2-source stacked tile (rows 0..63 from b0, 64..127
// from b1, row stride 128 words).  2048 x 16B chunks per half, 8 per thread.
__device__ __forceinline__ void fill_w(uint32_t swb, const uint32_t* __restrict__ b0,
                                       const uint32_t* __restrict__ b1, int h, int t) {
    const int co = h * 64;
    #pragma unroll
    for (int i = 0; i < 8; ++i) {
        int cid = t + (i << 8);
        int row = cid >> 4, j = (cid & 15) << 2;
        const uint32_t* src = ((row < 64) ? b0 + row * 128 : b1 + (row - 64) * 128) + co + j;
        cp16(swb + (uint32_t)(row * LDW + co + j) * 4u, src);
    }
}
// fill half 'h' of sW for Mcat: half h columns come from pw2tf[e_h] (row stride
// 64 words), placed at column offset h*64.
__device__ __forceinline__ void fill_m(uint32_t swb, const uint32_t* __restrict__ base,
                                       int h, int t) {
    const int co = h * 64;
    #pragma unroll
    for (int i = 0; i < 8; ++i) {
        int cid = t + (i << 8);
        int row = cid >> 4, j = (cid & 15) << 2;
        cp16(swb + (uint32_t)(row * LDW + co + j) * 4u, base + row * 64 + j);
    }
}
// fill half 'h' of sW from proj (single source, row stride 128)
__device__ __forceinline__ void fill_p(uint32_t swb, const uint32_t* __restrict__ base,
                                       int h, int t) {
    const int co = h * 64;
    #pragma unroll
    for (int i = 0; i < 8; ++i) {
        int cid = t + (i << 8);
        int row = cid >> 4, j = (cid & 15) << 2;
        cp16(swb + (uint32_t)(row * LDW + co + j) * 4u, base + row * 128 + co + j);
    }
}

__device__ __forceinline__ void stage_act(uint32_t* sA, const float* __restrict__ gsrc, int t) {
    #pragma unroll
    for (int f = t; f < 4096; f += 256) {
        int c = f >> 5, q = f & 31;
        float4 u = *(const float4*)(gsrc + (size_t)c * NHW + q * 4);
        uint4 w;
        w.x = f2tf(u.x); w.y = f2tf(u.y); w.z = f2tf(u.z); w.w = f2tf(u.w);
        *(uint4*)(sA + c * LDX + q * 4) = w;
    }
}

// half-K GEMM: acc += W[m, k in half] * B[k in half, n]
__device__ __forceinline__ void gemm_half(const uint32_t* __restrict__ sW,
                                          const uint32_t* __restrict__ sB,
                                          float acc[2][8][4], int m0, int n0, int lane, int h) {
    const int ar = lane >> 2, ac = lane & 3;
    #pragma unroll
    for (int kk = h * 8; kk < h * 8 + 8; ++kk) {
        const int k0 = kk << 3;
        uint32_t a[2][4];
        #pragma unroll
        for (int mf = 0; mf < 2; ++mf) {
            const uint32_t* pa = sW + (m0 + mf * 16 + ar) * LDW + k0 + ac;
            a[mf][0] = pa[0];
            a[mf][2] = pa[4];
            a[mf][1] = pa[8 * LDW];
            a[mf][3] = pa[8 * LDW + 4];
        }
        #pragma unroll
        for (int nf = 0; nf < 8; ++nf) {
            const uint32_t* pb = sB + (k0 + ac) * LDX + n0 + nf * 8 + ar;
            uint32_t b[2];
            b[0] = pb[0];
            b[1] = pb[4 * LDX];
            mma_tf32(acc[0][nf], a[0], b);
            mma_tf32(acc[1][nf], a[1], b);
        }
    }
}

#define ZERO_ACC(A) \
    { _Pragma("unroll") for (int i = 0; i < 2; ++i) \
      _Pragma("unroll") for (int j = 0; j < 8; ++j) \
      _Pragma("unroll") for (int kq = 0; kq < 4; ++kq) (A)[i][j][kq] = 0.f; }

__global__ __launch_bounds__(256, 1) void main_mma_kernel(
    const float* __restrict__ x, const float* __restrict__ sh,
    float* __restrict__ out) {
    extern __shared__ uint32_t smem[];
    uint32_t* sX = smem + SM_X;
    uint32_t* sS = smem + SM_S;     // later reused for T
    uint32_t* sW = smem + SM_W;

    const int t = threadIdx.x;
    const int lane = t & 31;
    const int wid = t >> 5;
    const int m0 = (wid >> 1) << 5;          // 0,32,64,96
    const int n0 = (wid & 1) << 6;           // 0,64
    const int b = blockIdx.y;
    const int hw0 = blockIdx.x * 128;

    const int   e0  = g_sel[b * 2],  e1  = g_sel[b * 2 + 1];
    const float ga0 = g_gate[b * 2], ga1 = g_gate[b * 2 + 1];
    const float gs  = g_gsum[b];

    const uint32_t swb = (uint32_t)__cvta_generic_to_shared(sW);
    const uint32_t* w0a = g_w0tf + (size_t)e0 * NR * NC;
    const uint32_t* w0b = g_w0tf + (size_t)e1 * NR * NC;
    const uint32_t* w1a = g_w1tf + (size_t)e0 * NR * NC;
    const uint32_t* w1b = g_w1tf + (size_t)e1 * NR * NC;
    const uint32_t* m0p = g_pw2tf + (size_t)e0 * NC * NR;
    const uint32_t* m1p = g_pw2tf + (size_t)e1 * NC * NR;

    const float* xb = x  + (size_t)b * NC * NHW + hw0;
    const float* sb = sh + (size_t)b * NC * NHW + hw0;

    // prologue: queue both halves of Wcat0, stage activations meanwhile
    fill_w(swb, w0a, w0b, 0, t); CP_COMMIT();   // c0 -> H0
    fill_w(swb, w0a, w0b, 1, t); CP_COMMIT();   // c1 -> H1
    stage_act(sX, xb, t);
    stage_act(sS, sb, t);
    CP_WAIT1(); __syncthreads();                // c0 done; acts visible

    float accA[2][8][4]; ZERO_ACC(accA);
    float accG[2][8][4]; ZERO_ACC(accG);
    float accO[2][8][4]; ZERO_ACC(accO);

    // P0 H0: accA += W0 @ X (k 0-63)
    gemm_half(sW, sX, accA, m0, n0, lane, 0);
    __syncthreads();
    fill_w(swb, w1a, w1b, 0, t); CP_COMMIT();   // c2 -> H0 (W1)
    CP_WAIT1(); __syncthreads();                // c1 done
    // P0 H1
    gemm_half(sW, sX, accA, m0, n0, lane, 1);
    __syncthreads();
    fill_w(swb, w1a, w1b, 1, t); CP_COMMIT();   // c3 -> H1 (W1)
    CP_WAIT1(); __syncthreads();                // c2 done
    // P1 H0: accG += W1 @ S
    gemm_half(sW, sS, accG, m0, n0, lane, 0);
    __syncthreads();
    fill_m(swb, m0p, 0, t); CP_COMMIT();        // c4 -> H0 (Mcat lo)
    CP_WAIT1(); __syncthreads();                // c3 done
    // P1 H1
    gemm_half(sW, sS, accG, m0, n0, lane, 1);
    __syncthreads();                            // all warps done reading sS (as S)
    fill_m(swb, m1p, 1, t); CP_COMMIT();        // c5 -> H1 (Mcat hi)

    // T = ga(row) * accA * silu(accG) -> sS (k = stacked rank)
    {
        const int ar = lane >> 2, ac = lane & 3;
        #pragma unroll
        for (int mf = 0; mf < 2; ++mf) {
            const float ga = ((m0 + mf * 16) < 64) ? ga0 : ga1;
            #pragma unroll
            for (int nf = 0; nf < 8; ++nf) {
                const int col = n0 + nf * 8 + 2 * ac;
                #pragma unroll
                for (int half = 0; half < 2; ++half) {
                    const int row = m0 + mf * 16 + ar + half * 8;
                    float a0 = accA[mf][nf][half * 2 + 0];
                    float a1 = accA[mf][nf][half * 2 + 1];
                    float g0 = accG[mf][nf][half * 2 + 0];
                    float g1 = accG[mf][nf][half * 2 + 1];
                    uint2 w;
                    w.x = f2tf(ga * a0 * (g0 / (1.f + __expf(-g0))));
                    w.y = f2tf(ga * a1 * (g1 / (1.f + __expf(-g1))));
                    *(uint2*)(sS + row * LDX + col) = w;
                }
            }
        }
    }
    ZERO_ACC(accA);                             // accA reused for GEMM4
    CP_WAIT1(); __syncthreads();                // c4 done; T visible
    // P2 H0: accO += Mcat @ T
    gemm_half(sW, sS, accO, m0, n0, lane, 0);
    __syncthreads();
    fill_p(swb, g_projtf, 0, t); CP_COMMIT();   // c6 -> H0 (proj)
    CP_WAIT1(); __syncthreads();                // c5 done
    // P2 H1
    gemm_half(sW, sS, accO, m0, n0, lane, 1);
    __syncthreads();
    fill_p(swb, g_projtf, 1, t); CP_COMMIT();   // c7 -> H1 (proj)
    CP_WAIT1(); __syncthreads();                // c6 done
    // P3 H0: accA += proj @ X
    gemm_half(sW, sX, accA, m0, n0, lane, 0);
    CP_WAIT0(); __syncthreads();                // c7 done
    // P3 H1
    gemm_half(sW, sX, accA, m0, n0, lane, 1);

    // epilogue: out = accO + gs * accA
    {
        const int ar = lane >> 2, ac = lane & 3;
        float* ob = out + (size_t)b * NC * NHW + hw0;
        #pragma unroll
        for (int mf = 0; mf < 2; ++mf) {
            #pragma unroll
            for (int nf = 0; nf < 8; ++nf) {
                const int col = n0 + nf * 8 + 2 * ac;
                #pragma unroll
                for (int half = 0; half < 2; ++half) {
                    const int row = m0 + mf * 16 + ar + half * 8;
                    float2 v = make_float2(
                        accO[mf][nf][half * 2 + 0] + gs * accA[mf][nf][half * 2 + 0],
                        accO[mf][nf][half * 2 + 1] + gs * accA[mf][nf][half * 2 + 1]);
                    *(float2*)(ob + (size_t)row * NHW + col) = v;
                }
            }
        }
    }
}

// ---------------------------------------------------------------------------
extern "C" void kernel_launch(void* const* d_in, const int* in_sizes, int n_in,
                              void* d_out, int out_size) {
    const float* x       = (const float*)d_in[0];
    const float* sh      = (const float*)d_in[1];
    const float* mlp_w1  = (const float*)d_in[2];
    const float* mlp_b1  = (const float*)d_in[3];
    const float* mlp_w2  = (const float*)d_in[4];
    const float* mlp_b2  = (const float*)d_in[5];
    const float* gate_w  = (const float*)d_in[6];
    const float* fgate_w = (const float*)d_in[7];
    const float* exp_w0  = (const float*)d_in[8];
    const float* exp_w1  = (const float*)d_in[9];
    const float* exp_w2  = (const float*)d_in[10];
    const float* proj_w  = (const float*)d_in[11];
    float* out = (float*)d_out;

    cudaFuncSetAttribute(main_mma_kernel, cudaFuncAttributeMaxDynamicSharedMemorySize, SMEM_MAIN);

    conv_pw2_kernel<<<660, 256>>>(x, exp_w2, proj_w, exp_w0, exp_w1);
    routing_kernel<<<NB, 256>>>(mlp_w1, mlp_b1, mlp_w2, mlp_b2, gate_w, fgate_w);
    main_mma_kernel<<<dim3(NHW / 128, NB), 256, SMEM_MAIN>>>(x, sh, out);
}

// round 12
// speedup vs baseline: 1.4816x; 1.0078x over previous
#include <cuda_runtime.h>
#include <math.h>
#include <stdint.h>

// Problem constants
#define NB 8
#define NC 128
#define NHW 16384
#define NE 4
#define NR 64

// smem layout (words) for main kernel — R3 proven layout
#define LDW 132           // weight tile ld  (conflict-free A ldsm + STS)
#define LDX 136           // act tile ld     (conflict-free B-frag LDS)
#define SM_X 0
#define SM_S (128 * LDX)
#define SM_W (2 * 128 * LDX)
#define SMEM_MAIN ((2 * 128 * LDX + 128 * LDW) * 4)   // 206848 bytes

// ---------------- device scratch ----------------
__device__ float g_fe0[NB * NC];
__device__ float g_pooled[NB * NC];
__device__ int   g_sel[NB * 2];
__device__ float g_gate[NB * 2];
__device__ float g_gsum[NB];
// pre-converted tf32 weight tiles (batch-independent)
__device__ __align__(16) uint32_t g_w0tf[NE * NR * NC];    // [e][r][c]
__device__ __align__(16) uint32_t g_w1tf[NE * NR * NC];    // [e][r][c]
__device__ __align__(16) uint32_t g_pw2tf[NE * NC * NR];   // [e][d][r], unscaled
__device__ __align__(16) uint32_t g_projtf[NC * NC];       // [d][c], unscaled

__device__ __forceinline__ float gelu_f(float v) {
    return 0.5f * v * (1.0f + erff(v * 0.70710678118654752440f));
}
__device__ __forceinline__ float gelu_fast(float v) {
    float u = 0.7978845608f * (v + 0.044715f * v * v * v);
    float th;
    asm("tanh.approx.f32 %0, %1;" : "=f"(th) : "f"(u));
    return 0.5f * v * (1.0f + th);
}
__device__ __forceinline__ uint32_t f2tf(float f) {
    uint32_t r; asm("cvt.rna.tf32.f32 %0, %1;" : "=r"(r) : "f"(f)); return r;
}
__device__ __forceinline__ void mma_tf32(float* c, const uint32_t* a, const uint32_t* b) {
    asm volatile(
        "mma.sync.aligned.m16n8k8.row.col.f32.tf32.tf32.f32 "
        "{%0,%1,%2,%3}, {%4,%5,%6,%7}, {%8,%9}, {%0,%1,%2,%3};"
        : "+f"(c[0]), "+f"(c[1]), "+f"(c[2]), "+f"(c[3])
        : "r"(a[0]), "r"(a[1]), "r"(a[2]), "r"(a[3]), "r"(b[0]), "r"(b[1]));
}
// ldmatrix x4: A-fragment load (non-transposed, b16 pairs == tf32 elements)
__device__ __forceinline__ void ldsm4(uint32_t* r, uint32_t saddr) {
    asm volatile("ldmatrix.sync.aligned.m8n8.x4.shared.b16 {%0,%1,%2,%3}, [%4];"
        : "=r"(r[0]), "=r"(r[1]), "=r"(r[2]), "=r"(r[3]) : "r"(saddr));
}
__device__ __forceinline__ void cp16(uint32_t saddr, const uint32_t* g) {
    asm volatile("{ .reg .u64 ga; cvta.to.global.u64 ga, %1; "
                 "cp.async.ca.shared.global [%0], [ga], 16; }"
                 :: "r"(saddr), "l"(g) : "memory");
}
#define CP_COMMIT() asm volatile("cp.async.commit_group;" ::: "memory")
#define CP_WAIT1()  asm volatile("cp.async.wait_group 1;" ::: "memory")
#define CP_WAIT0()  asm volatile("cp.async.wait_group 0;" ::: "memory")

// ---------------------------------------------------------------------------
// Kernel 1 (fused): [0,512) conv stencil; [512,640) PW2->tf32; [640,660)
//   linear tf32 conversion of exp_w0 / exp_w1 / proj_w.
// ---------------------------------------------------------------------------
__global__ __launch_bounds__(256) void conv_pw2_kernel(
    const float* __restrict__ x, const float* __restrict__ exp_w2,
    const float* __restrict__ proj_w, const float* __restrict__ exp_w0,
    const float* __restrict__ exp_w1) {
    const int t = threadIdx.x;
    if (blockIdx.x >= 640) {
        int c = blockIdx.x - 640;
        const float* src;
        uint32_t* dst;
        if (c < 8)       { src = exp_w0 + c * 4096;        dst = g_w0tf + c * 4096; }
        else if (c < 16) { src = exp_w1 + (c - 8) * 4096;  dst = g_w1tf + (c - 8) * 4096; }
        else             { src = proj_w + (c - 16) * 4096; dst = g_projtf + (c - 16) * 4096; }
        #pragma unroll
        for (int i = 0; i < 4; ++i) {
            int f = t + (i << 8);
            float4 u = ((const float4*)src)[f];
            uint4 w;
            w.x = f2tf(u.x); w.y = f2tf(u.y); w.z = f2tf(u.z); w.w = f2tf(u.w);
            ((uint4*)dst)[f] = w;
        }
        return;
    }
    if (blockIdx.x >= 512) {
        int bi = blockIdx.x - 512;
        int e = bi >> 5;
        int d = ((bi & 31) << 2) + (t >> 6);
        int r = t & 63;
        const float* pw = proj_w + d * NC;
        const float* w2 = exp_w2 + (size_t)e * NC * NR + r;
        float a = 0.f;
        #pragma unroll 8
        for (int c = 0; c < NC; ++c) a += pw[c] * w2[c * NR];
        g_pw2tf[(e * NC + d) * NR + r] = f2tf(a);
        return;
    }

    // ---- conv stencil: 2 planes/block, rolling registers, shfl halos ----
    const int wid = t >> 5, lane = t & 31;
    const int plane = blockIdx.x * 2 + (wid >> 2);
    const int w4 = wid & 3;
    const float* p = x + (size_t)plane * NHW + lane * 4;
    const int r0 = w4 * 32;

    const float4 z = make_float4(0.f, 0.f, 0.f, 0.f);
    float4 prev = (r0 > 0) ? *(const float4*)(p + (r0 - 1) * 128) : z;
    float4 cur  = *(const float4*)(p + r0 * 128);
    float4 nxt  = *(const float4*)(p + (r0 + 1) * 128);
    float4 nxt2 = *(const float4*)(p + (r0 + 2) * 128);

    float sumg = 0.f, sumx = 0.f;
    #pragma unroll 4
    for (int i = 0; i < 32; ++i) {
        int rn = r0 + i + 3;
        float4 inc = (rn < 128) ? *(const float4*)(p + rn * 128) : z;

        sumx += cur.x + cur.y + cur.z + cur.w;

        float pl = __shfl_up_sync(0xffffffffu, prev.w, 1);
        float cl = __shfl_up_sync(0xffffffffu, cur.w, 1);
        float nl = __shfl_up_sync(0xffffffffu, nxt.w, 1);
        float pr = __shfl_down_sync(0xffffffffu, prev.x, 1);
        float cr = __shfl_down_sync(0xffffffffu, cur.x, 1);
        float nr = __shfl_down_sync(0xffffffffu, nxt.x, 1);
        if (lane == 0)  { pl = 0.f; cl = 0.f; nl = 0.f; }
        if (lane == 31) { pr = 0.f; cr = 0.f; nr = 0.f; }

        float nb0 = pl + prev.x + prev.y + cl + cur.y + nl + nxt.x + nxt.y;
        float nb1 = prev.x + prev.y + prev.z + cur.x + cur.z + nxt.x + nxt.y + nxt.z;
        float nb2 = prev.y + prev.z + prev.w + cur.y + cur.w + nxt.y + nxt.z + nxt.w;
        float nb3 = prev.z + prev.w + pr + cur.z + cr + nxt.z + nxt.w + nr;

        sumg += gelu_fast(8.f * cur.x - nb0);
        sumg += gelu_fast(8.f * cur.y - nb1);
        sumg += gelu_fast(8.f * cur.z - nb2);
        sumg += gelu_fast(8.f * cur.w - nb3);

        prev = cur; cur = nxt; nxt = nxt2; nxt2 = inc;
    }

    for (int o = 16; o > 0; o >>= 1) {
        sumg += __shfl_down_sync(0xffffffffu, sumg, o);
        sumx += __shfl_down_sync(0xffffffffu, sumx, o);
    }
    __shared__ float rg[8], rx[8];
    if (lane == 0) { rg[wid] = sumg; rx[wid] = sumx; }
    __syncthreads();
    if (t < 2) {
        float ag = 0.f, ax = 0.f;
        #pragma unroll
        for (int i = 0; i < 4; ++i) { ag += rg[t * 4 + i]; ax += rx[t * 4 + i]; }
        const float inv = 1.0f / 16384.0f;
        int pl = blockIdx.x * 2 + t;
        g_fe0[pl]    = ag * inv;
        g_pooled[pl] = ax * inv;
    }
}

// ---------------------------------------------------------------------------
// Kernel 2: routing, one block per batch
// ---------------------------------------------------------------------------
__global__ __launch_bounds__(256) void routing_kernel(
    const float* __restrict__ mlp_w1, const float* __restrict__ mlp_b1,
    const float* __restrict__ mlp_w2, const float* __restrict__ mlp_b2,
    const float* __restrict__ gate_w, const float* __restrict__ fgate_w) {
    __shared__ float s_in[NC], s_pool[NC], s_h1[256], s_fe[NC], s_log[NE];
    const int b = blockIdx.x;
    const int t = threadIdx.x;

    if (t < NC) { s_in[t] = g_fe0[b * NC + t]; s_pool[t] = g_pooled[b * NC + t]; }
    __syncthreads();
    {
        float a = mlp_b1[t];
        #pragma unroll 8
        for (int c = 0; c < NC; ++c) a += s_in[c] * mlp_w1[c * 256 + t];
        s_h1[t] = gelu_f(a);
    }
    __syncthreads();
    if (t < NC) {
        float a = mlp_b2[t];
        #pragma unroll 8
        for (int c = 0; c < 256; ++c) a += s_h1[c] * mlp_w2[c * NC + t];
        s_fe[t] = a;
    }
    __syncthreads();
    if (t < NE) {
        float a = 0.f;
        for (int c = 0; c < NC; ++c)
            a += s_pool[c] * gate_w[c * NE + t] + s_fe[c] * fgate_w[c * NE + t];
        s_log[t] = a;
    }
    __syncthreads();
    if (t == 0) {
        float sc[NE];
        float m = -1e30f;
        #pragma unroll
        for (int e = 0; e < NE; ++e) { sc[e] = s_log[e]; m = fmaxf(m, sc[e]); }
        float ss = 0.f;
        #pragma unroll
        for (int e = 0; e < NE; ++e) { sc[e] = expf(sc[e] - m); ss += sc[e]; }
        float inv = 1.0f / ss;
        #pragma unroll
        for (int e = 0; e < NE; ++e) sc[e] *= inv;
        int i0 = 0;
        #pragma unroll
        for (int e = 1; e < NE; ++e) if (sc[e] > sc[i0]) i0 = e;
        int i1 = -1;
        #pragma unroll
        for (int e = 0; e < NE; ++e) {
            if (e == i0) continue;
            if (i1 < 0 || sc[e] > sc[i1]) i1 = e;
        }
        g_sel[b * 2] = i0;  g_sel[b * 2 + 1] = i1;
        g_gate[b * 2] = sc[i0]; g_gate[b * 2 + 1] = sc[i1];
        g_gsum[b] = sc[i0] + sc[i1];
    }
}

// ---------------------------------------------------------------------------
// Main tensor-core kernel — cp.async K-half double-buffering + ldsm A-frags.
// ---------------------------------------------------------------------------

__device__ __forceinline__ void fill_w(uint32_t swb, const uint32_t* __restrict__ b0,
                                       const uint32_t* __restrict__ b1, int h, int t) {
    const int co = h * 64;
    #pragma unroll
    for (int i = 0; i < 8; ++i) {
        int cid = t + (i << 8);
        int row = cid >> 4, j = (cid & 15) << 2;
        const uint32_t* src = ((row < 64) ? b0 + row * 128 : b1 + (row - 64) * 128) + co + j;
        cp16(swb + (uint32_t)(row * LDW + co + j) * 4u, src);
    }
}
__device__ __forceinline__ void fill_m(uint32_t swb, const uint32_t* __restrict__ base,
                                       int h, int t) {
    const int co = h * 64;
    #pragma unroll
    for (int i = 0; i < 8; ++i) {
        int cid = t + (i << 8);
        int row = cid >> 4, j = (cid & 15) << 2;
        cp16(swb + (uint32_t)(row * LDW + co + j) * 4u, base + row * 64 + j);
    }
}
__device__ __forceinline__ void fill_p(uint32_t swb, const uint32_t* __restrict__ base,
                                       int h, int t) {
    const int co = h * 64;
    #pragma unroll
    for (int i = 0; i < 8; ++i) {
        int cid = t + (i << 8);
        int row = cid >> 4, j = (cid & 15) << 2;
        cp16(swb + (uint32_t)(row * LDW + co + j) * 4u, base + row * 128 + co + j);
    }
}

__device__ __forceinline__ void stage_act(uint32_t* sA, const float* __restrict__ gsrc, int t) {
    #pragma unroll
    for (int f = t; f < 4096; f += 256) {
        int c = f >> 5, q = f & 31;
        float4 u = *(const float4*)(gsrc + (size_t)c * NHW + q * 4);
        uint4 w;
        w.x = f2tf(u.x); w.y = f2tf(u.y); w.z = f2tf(u.z); w.w = f2tf(u.w);
        *(uint4*)(sA + c * LDX + q * 4) = w;
    }
}

// half-K GEMM: acc += W[m, k in half] * B[k in half, n]
// A-fragments via ldmatrix.x4: lane l supplies row pointer for matrix l>>3;
// matrices ordered (rows-lo,k-lo),(rows-hi,k-lo),(rows-lo,k-hi),(rows-hi,k-hi)
// so regs r0..r3 land exactly as mma operands a0..a3.
__device__ __forceinline__ void gemm_half(uint32_t swb,
                                          const uint32_t* __restrict__ sB,
                                          float acc[2][8][4], int m0, int n0, int lane, int h) {
    const int ar = lane >> 2, ac = lane & 3;
    const int mat = lane >> 3, r8 = lane & 7;
    // per-warp ldsm base (k=0) for each mf
    uint32_t abase[2];
    #pragma unroll
    for (int mf = 0; mf < 2; ++mf) {
        int row = m0 + mf * 16 + (mat & 1) * 8 + r8;
        int col = (mat >> 1) * 4;
        abase[mf] = swb + (uint32_t)(row * LDW + col) * 4u;
    }
    #pragma unroll
    for (int kk = h * 8; kk < h * 8 + 8; ++kk) {
        const int k0 = kk << 3;
        uint32_t a[2][4];
        ldsm4(a[0], abase[0] + (uint32_t)k0 * 4u);
        ldsm4(a[1], abase[1] + (uint32_t)k0 * 4u);
        #pragma unroll
        for (int nf = 0; nf < 8; ++nf) {
            const uint32_t* pb = sB + (k0 + ac) * LDX + n0 + nf * 8 + ar;
            uint32_t b[2];
            b[0] = pb[0];
            b[1] = pb[4 * LDX];
            mma_tf32(acc[0][nf], a[0], b);
            mma_tf32(acc[1][nf], a[1], b);
        }
    }
}

#define ZERO_ACC(A) \
    { _Pragma("unroll") for (int i = 0; i < 2; ++i) \
      _Pragma("unroll") for (int j = 0; j < 8; ++j) \
      _Pragma("unroll") for (int kq = 0; kq < 4; ++kq) (A)[i][j][kq] = 0.f; }

__global__ __launch_bounds__(256, 1) void main_mma_kernel(
    const float* __restrict__ x, const float* __restrict__ sh,
    float* __restrict__ out) {
    extern __shared__ uint32_t smem[];
    uint32_t* sX = smem + SM_X;
    uint32_t* sS = smem + SM_S;     // later reused for T
    uint32_t* sW = smem + SM_W;

    const int t = threadIdx.x;
    const int lane = t & 31;
    const int wid = t >> 5;
    const int m0 = (wid >> 1) << 5;          // 0,32,64,96
    const int n0 = (wid & 1) << 6;           // 0,64
    const int b = blockIdx.y;
    const int hw0 = blockIdx.x * 128;

    const int   e0  = g_sel[b * 2],  e1  = g_sel[b * 2 + 1];
    const float ga0 = g_gate[b * 2], ga1 = g_gate[b * 2 + 1];
    const float gs  = g_gsum[b];

    const uint32_t swb = (uint32_t)__cvta_generic_to_shared(sW);
    const uint32_t* w0a = g_w0tf + (size_t)e0 * NR * NC;
    const uint32_t* w0b = g_w0tf + (size_t)e1 * NR * NC;
    const uint32_t* w1a = g_w1tf + (size_t)e0 * NR * NC;
    const uint32_t* w1b = g_w1tf + (size_t)e1 * NR * NC;
    const uint32_t* m0p = g_pw2tf + (size_t)e0 * NC * NR;
    const uint32_t* m1p = g_pw2tf + (size_t)e1 * NC * NR;

    const float* xb = x  + (size_t)b * NC * NHW + hw0;
    const float* sb = sh + (size_t)b * NC * NHW + hw0;

    // prologue: queue both halves of Wcat0, stage activations meanwhile
    fill_w(swb, w0a, w0b, 0, t); CP_COMMIT();   // c0 -> H0
    fill_w(swb, w0a, w0b, 1, t); CP_COMMIT();   // c1 -> H1
    stage_act(sX, xb, t);
    stage_act(sS, sb, t);
    CP_WAIT1(); __syncthreads();                // c0 done; acts visible

    float accA[2][8][4]; ZERO_ACC(accA);
    float accG[2][8][4]; ZERO_ACC(accG);
    float accO[2][8][4]; ZERO_ACC(accO);

    // P0 H0: accA += W0 @ X (k 0-63)
    gemm_half(swb, sX, accA, m0, n0, lane, 0);
    __syncthreads();
    fill_w(swb, w1a, w1b, 0, t); CP_COMMIT();   // c2 -> H0 (W1)
    CP_WAIT1(); __syncthreads();                // c1 done
    // P0 H1
    gemm_half(swb, sX, accA, m0, n0, lane, 1);
    __syncthreads();
    fill_w(swb, w1a, w1b, 1, t); CP_COMMIT();   // c3 -> H1 (W1)
    CP_WAIT1(); __syncthreads();                // c2 done
    // P1 H0: accG += W1 @ S
    gemm_half(swb, sS, accG, m0, n0, lane, 0);
    __syncthreads();
    fill_m(swb, m0p, 0, t); CP_COMMIT();        // c4 -> H0 (Mcat lo)
    CP_WAIT1(); __syncthreads();                // c3 done
    // P1 H1
    gemm_half(swb, sS, accG, m0, n0, lane, 1);
    __syncthreads();                            // all warps done reading sS (as S)
    fill_m(swb, m1p, 1, t); CP_COMMIT();        // c5 -> H1 (Mcat hi)

    // T = ga(row) * accA * silu(accG) -> sS (k = stacked rank)
    {
        const int ar = lane >> 2, ac = lane & 3;
        #pragma unroll
        for (int mf = 0; mf < 2; ++mf) {
            const float ga = ((m0 + mf * 16) < 64) ? ga0 : ga1;
            #pragma unroll
            for (int nf = 0; nf < 8; ++nf) {
                const int col = n0 + nf * 8 + 2 * ac;
                #pragma unroll
                for (int half = 0; half < 2; ++half) {
                    const int row = m0 + mf * 16 + ar + half * 8;
                    float a0 = accA[mf][nf][half * 2 + 0];
                    float a1 = accA[mf][nf][half * 2 + 1];
                    float g0 = accG[mf][nf][half * 2 + 0];
                    float g1 = accG[mf][nf][half * 2 + 1];
                    uint2 w;
                    w.x = f2tf(ga * a0 * (g0 / (1.f + __expf(-g0))));
                    w.y = f2tf(ga * a1 * (g1 / (1.f + __expf(-g1))));
                    *(uint2*)(sS + row * LDX + col) = w;
                }
            }
        }
    }
    ZERO_ACC(accA);                             // accA reused for GEMM4 (proj)
    CP_WAIT1(); __syncthreads();                // c4 done; T visible
    // P2 H0: accO += Mcat @ T
    gemm_half(swb, sS, accO, m0, n0, lane, 0);
    __syncthreads();
    fill_p(swb, g_projtf, 0, t); CP_COMMIT();   // c6 -> H0 (proj)
    CP_WAIT1(); __syncthreads();                // c5 done
    // P2 H1
    gemm_half(swb, sS, accO, m0, n0, lane, 1);
    __syncthreads();
    fill_p(swb, g_projtf, 1, t); CP_COMMIT();   // c7 -> H1 (proj)
    CP_WAIT1(); __syncthreads();                // c6 done
    // P3 H0: accA += proj @ X
    gemm_half(swb, sX, accA, m0, n0, lane, 0);
    CP_WAIT0(); __syncthreads();                // c7 done
    // P3 H1
    gemm_half(swb, sX, accA, m0, n0, lane, 1);

    // epilogue: out = accO + gs * accA
    {
        const int ar = lane >> 2, ac = lane & 3;
        float* ob = out + (size_t)b * NC * NHW + hw0;
        #pragma unroll
        for (int mf = 0; mf < 2; ++mf) {
            #pragma unroll
            for (int nf = 0; nf < 8; ++nf) {
                const int col = n0 + nf * 8 + 2 * ac;
                #pragma unroll
                for (int half = 0; half < 2; ++half) {
                    const int row = m0 + mf * 16 + ar + half * 8;
                    float2 v = make_float2(
                        accO[mf][nf][half * 2 + 0] + gs * accA[mf][nf][half * 2 + 0],
                        accO[mf][nf][half * 2 + 1] + gs * accA[mf][nf][half * 2 + 1]);
                    *(float2*)(ob + (size_t)row * NHW + col) = v;
                }
            }
        }
    }
}

// ---------------------------------------------------------------------------
extern "C" void kernel_launch(void* const* d_in, const int* in_sizes, int n_in,
                              void* d_out, int out_size) {
    const float* x       = (const float*)d_in[0];
    const float* sh      = (const float*)d_in[1];
    const float* mlp_w1  = (const float*)d_in[2];
    const float* mlp_b1  = (const float*)d_in[3];
    const float* mlp_w2  = (const float*)d_in[4];
    const float* mlp_b2  = (const float*)d_in[5];
    const float* gate_w  = (const float*)d_in[6];
    const float* fgate_w = (const float*)d_in[7];
    const float* exp_w0  = (const float*)d_in[8];
    const float* exp_w1  = (const float*)d_in[9];
    const float* exp_w2  = (const float*)d_in[10];
    const float* proj_w  = (const float*)d_in[11];
    float* out = (float*)d_out;

    cudaFuncSetAttribute(main_mma_kernel, cudaFuncAttributeMaxDynamicSharedMemorySize, SMEM_MAIN);

    conv_pw2_kernel<<<660, 256>>>(x, exp_w2, proj_w, exp_w0, exp_w1);
    routing_kernel<<<NB, 256>>>(mlp_w1, mlp_b1, mlp_w2, mlp_b2, gate_w, fgate_w);
    main_mma_kernel<<<dim3(NHW / 128, NB), 256, SMEM_MAIN>>>(x, sh, out);
}

// round 13
// speedup vs baseline: 1.8834x; 1.2712x over previous
#include <cuda_runtime.h>
#include <cuda_fp16.h>
#include <math.h>
#include <stdint.h>

// Problem constants
#define NB 8
#define NC 128
#define NHW 16384
#define NE 4
#define NR 64

// All main-kernel tiles: 128 rows x 68 words (136 halves). Word offsets:
#define LDH 68
#define RA  0        // X acts [px][k]  (later reused for T)
#define RS  8704     // S acts [px][k]
#define RW0 17408    // W0cat  [m][k]
#define RPJ 26112    // proj   [m][k]
#define RW1 34816    // W1cat  [m][k]
#define RMC 43520    // Mcat   [d][rank]
#define SMEM_MAIN (52224 * 4)   // 208896 bytes

// ---------------- device scratch ----------------
__device__ float g_fe0[NB * NC];
__device__ float g_pooled[NB * NC];
__device__ int   g_sel[NB * 2];
__device__ float g_gate[NB * 2];
__device__ float g_gsum[NB];
// pre-converted fp16 weights (packed half2 words, +slack for cp alignment)
__device__ __align__(16) uint32_t g_w0h[NE * NR * 64 + 8];   // [e][r][64w]
__device__ __align__(16) uint32_t g_w1h[NE * NR * 64 + 8];
__device__ __align__(16) uint32_t g_pw2h[NE * NC * 32 + 8];  // [e][d][32w]
__device__ __align__(16) uint32_t g_projh[NC * 64 + 8];      // [d][64w]

__device__ __forceinline__ float gelu_f(float v) {
    return 0.5f * v * (1.0f + erff(v * 0.70710678118654752440f));
}
__device__ __forceinline__ float gelu_fast(float v) {
    float u = 0.7978845608f * (v + 0.044715f * v * v * v);
    float th;
    asm("tanh.approx.f32 %0, %1;" : "=f"(th) : "f"(u));
    return 0.5f * v * (1.0f + th);
}
__device__ __forceinline__ uint32_t pack2(float a, float b) {
    __half2 h = __floats2half2_rn(a, b);
    return *(uint32_t*)&h;
}
__device__ __forceinline__ void mma_f16(float* c, const uint32_t* a, uint32_t b0, uint32_t b1) {
    asm volatile(
        "mma.sync.aligned.m16n8k16.row.col.f32.f16.f16.f32 "
        "{%0,%1,%2,%3}, {%4,%5,%6,%7}, {%8,%9}, {%0,%1,%2,%3};"
        : "+f"(c[0]), "+f"(c[1]), "+f"(c[2]), "+f"(c[3])
        : "r"(a[0]), "r"(a[1]), "r"(a[2]), "r"(a[3]), "r"(b0), "r"(b1));
}
__device__ __forceinline__ void ldsm4(uint32_t* r, uint32_t saddr) {
    asm volatile("ldmatrix.sync.aligned.m8n8.x4.shared.b16 {%0,%1,%2,%3}, [%4];"
        : "=r"(r[0]), "=r"(r[1]), "=r"(r[2]), "=r"(r[3]) : "r"(saddr));
}
__device__ __forceinline__ void cp16(uint32_t saddr, const uint32_t* g) {
    asm volatile("{ .reg .u64 ga; cvta.to.global.u64 ga, %1; "
                 "cp.async.ca.shared.global [%0], [ga], 16; }"
                 :: "r"(saddr), "l"(g) : "memory");
}
#define CP_COMMIT() asm volatile("cp.async.commit_group;" ::: "memory")
#define CP_WAIT0()  asm volatile("cp.async.wait_group 0;" ::: "memory")

// ---------------------------------------------------------------------------
// Kernel 1 (fused): [0,512) conv stencil; [512,640) PW2 -> fp16;
//   [640,660) fp16 pack of exp_w0 / exp_w1 / proj_w.
// ---------------------------------------------------------------------------
__global__ __launch_bounds__(256) void conv_pw2_kernel(
    const float* __restrict__ x, const float* __restrict__ exp_w2,
    const float* __restrict__ proj_w, const float* __restrict__ exp_w0,
    const float* __restrict__ exp_w1) {
    const int t = threadIdx.x;
    if (blockIdx.x >= 640) {
        int c = blockIdx.x - 640;
        const float* src;
        uint32_t* dst;
        if (c < 8)       { src = exp_w0 + c * 4096;        dst = g_w0h + c * 2048; }
        else if (c < 16) { src = exp_w1 + (c - 8) * 4096;  dst = g_w1h + (c - 8) * 2048; }
        else             { src = proj_w + (c - 16) * 4096; dst = g_projh + (c - 16) * 2048; }
        #pragma unroll
        for (int i = 0; i < 4; ++i) {
            int f = t + (i << 8);
            float4 u = ((const float4*)src)[f];
            uint2 w;
            w.x = pack2(u.x, u.y);
            w.y = pack2(u.z, u.w);
            ((uint2*)dst)[f] = w;
        }
        return;
    }
    if (blockIdx.x >= 512) {
        int bi = blockIdx.x - 512;
        int e = bi >> 5;
        int d = ((bi & 31) << 2) + (t >> 6);
        int r = t & 63;
        const float* pw = proj_w + d * NC;
        const float* w2 = exp_w2 + (size_t)e * NC * NR + r;
        float a = 0.f;
        #pragma unroll 8
        for (int c = 0; c < NC; ++c) a += pw[c] * w2[c * NR];
        ((__half*)g_pw2h)[(e * NC + d) * NR + r] = __float2half_rn(a);
        return;
    }

    // ---- conv stencil: 2 planes/block, rolling registers, shfl halos ----
    const int wid = t >> 5, lane = t & 31;
    const int plane = blockIdx.x * 2 + (wid >> 2);
    const int w4 = wid & 3;
    const float* p = x + (size_t)plane * NHW + lane * 4;
    const int r0 = w4 * 32;

    const float4 z = make_float4(0.f, 0.f, 0.f, 0.f);
    float4 prev = (r0 > 0) ? *(const float4*)(p + (r0 - 1) * 128) : z;
    float4 cur  = *(const float4*)(p + r0 * 128);
    float4 nxt  = *(const float4*)(p + (r0 + 1) * 128);
    float4 nxt2 = *(const float4*)(p + (r0 + 2) * 128);

    float sumg = 0.f, sumx = 0.f;
    #pragma unroll 4
    for (int i = 0; i < 32; ++i) {
        int rn = r0 + i + 3;
        float4 inc = (rn < 128) ? *(const float4*)(p + rn * 128) : z;

        sumx += cur.x + cur.y + cur.z + cur.w;

        float pl = __shfl_up_sync(0xffffffffu, prev.w, 1);
        float cl = __shfl_up_sync(0xffffffffu, cur.w, 1);
        float nl = __shfl_up_sync(0xffffffffu, nxt.w, 1);
        float pr = __shfl_down_sync(0xffffffffu, prev.x, 1);
        float cr = __shfl_down_sync(0xffffffffu, cur.x, 1);
        float nr = __shfl_down_sync(0xffffffffu, nxt.x, 1);
        if (lane == 0)  { pl = 0.f; cl = 0.f; nl = 0.f; }
        if (lane == 31) { pr = 0.f; cr = 0.f; nr = 0.f; }

        float nb0 = pl + prev.x + prev.y + cl + cur.y + nl + nxt.x + nxt.y;
        float nb1 = prev.x + prev.y + prev.z + cur.x + cur.z + nxt.x + nxt.y + nxt.z;
        float nb2 = prev.y + prev.z + prev.w + cur.y + cur.w + nxt.y + nxt.z + nxt.w;
        float nb3 = prev.z + prev.w + pr + cur.z + cr + nxt.z + nxt.w + nr;

        sumg += gelu_fast(8.f * cur.x - nb0);
        sumg += gelu_fast(8.f * cur.y - nb1);
        sumg += gelu_fast(8.f * cur.z - nb2);
        sumg += gelu_fast(8.f * cur.w - nb3);

        prev = cur; cur = nxt; nxt = nxt2; nxt2 = inc;
    }

    for (int o = 16; o > 0; o >>= 1) {
        sumg += __shfl_down_sync(0xffffffffu, sumg, o);
        sumx += __shfl_down_sync(0xffffffffu, sumx, o);
    }
    __shared__ float rg[8], rx[8];
    if (lane == 0) { rg[wid] = sumg; rx[wid] = sumx; }
    __syncthreads();
    if (t < 2) {
        float ag = 0.f, ax = 0.f;
        #pragma unroll
        for (int i = 0; i < 4; ++i) { ag += rg[t * 4 + i]; ax += rx[t * 4 + i]; }
        const float inv = 1.0f / 16384.0f;
        int pl = blockIdx.x * 2 + t;
        g_fe0[pl]    = ag * inv;
        g_pooled[pl] = ax * inv;
    }
}

// ---------------------------------------------------------------------------
// Kernel 2: routing, one block per batch
// ---------------------------------------------------------------------------
__global__ __launch_bounds__(256) void routing_kernel(
    const float* __restrict__ mlp_w1, const float* __restrict__ mlp_b1,
    const float* __restrict__ mlp_w2, const float* __restrict__ mlp_b2,
    const float* __restrict__ gate_w, const float* __restrict__ fgate_w) {
    __shared__ float s_in[NC], s_pool[NC], s_h1[256], s_fe[NC], s_log[NE];
    const int b = blockIdx.x;
    const int t = threadIdx.x;

    if (t < NC) { s_in[t] = g_fe0[b * NC + t]; s_pool[t] = g_pooled[b * NC + t]; }
    __syncthreads();
    {
        float a = mlp_b1[t];
        #pragma unroll 8
        for (int c = 0; c < NC; ++c) a += s_in[c] * mlp_w1[c * 256 + t];
        s_h1[t] = gelu_f(a);
    }
    __syncthreads();
    if (t < NC) {
        float a = mlp_b2[t];
        #pragma unroll 8
        for (int c = 0; c < 256; ++c) a += s_h1[c] * mlp_w2[c * NC + t];
        s_fe[t] = a;
    }
    __syncthreads();
    if (t < NE) {
        float a = 0.f;
        for (int c = 0; c < NC; ++c)
            a += s_pool[c] * gate_w[c * NE + t] + s_fe[c] * fgate_w[c * NE + t];
        s_log[t] = a;
    }
    __syncthreads();
    if (t == 0) {
        float sc[NE];
        float m = -1e30f;
        #pragma unroll
        for (int e = 0; e < NE; ++e) { sc[e] = s_log[e]; m = fmaxf(m, sc[e]); }
        float ss = 0.f;
        #pragma unroll
        for (int e = 0; e < NE; ++e) { sc[e] = expf(sc[e] - m); ss += sc[e]; }
        float inv = 1.0f / ss;
        #pragma unroll
        for (int e = 0; e < NE; ++e) sc[e] *= inv;
        int i0 = 0;
        #pragma unroll
        for (int e = 1; e < NE; ++e) if (sc[e] > sc[i0]) i0 = e;
        int i1 = -1;
        #pragma unroll
        for (int e = 0; e < NE; ++e) {
            if (e == i0) continue;
            if (i1 < 0 || sc[e] > sc[i1]) i1 = e;
        }
        g_sel[b * 2] = i0;  g_sel[b * 2 + 1] = i1;
        g_gate[b * 2] = sc[i0]; g_gate[b * 2 + 1] = sc[i1];
        g_gsum[b] = sc[i0] + sc[i1];
    }
}

// ---------------------------------------------------------------------------
// Main fp16 tensor-core kernel: all tiles resident, 2 mid-kernel syncs.
// ---------------------------------------------------------------------------

// stage activations [128 c][128 px] f32 -> [px][k packed half2] in smem
__device__ __forceinline__ void stage_act_h(uint32_t* smw, const float* __restrict__ gsrc, int t) {
    #pragma unroll
    for (int i = 0; i < 16; ++i) {
        int unit = t + (i << 8);
        int px = (unit & 31) + 32 * ((unit >> 5) & 3);
        int cq = unit >> 7;                        // 0..31, c = 4cq..4cq+3
        const float* g = gsrc + (size_t)(4 * cq) * NHW + px;
        float v0 = g[0];
        float v1 = g[NHW];
        float v2 = g[2 * NHW];
        float v3 = g[3 * NHW];
        uint2 w;
        w.x = pack2(v0, v1);
        w.y = pack2(v2, v3);
        *(uint2*)(smw + px * LDH + 2 * cq) = w;
    }
}

// one M=128 GEMM: acc += W[m][k] * B[k][n]  (fp16, K=128, 8 k16-steps)
__device__ __forceinline__ void gemm_1(uint32_t smb, int aoff, const uint32_t* __restrict__ sB,
                                       float acc[2][8][4], int m0, int n0, int lane) {
    const int ar = lane >> 2, ac = lane & 3;
    const int mat = lane >> 3, r8 = lane & 7;
    uint32_t ab[2];
    #pragma unroll
    for (int mf = 0; mf < 2; ++mf) {
        int row = m0 + mf * 16 + (mat & 1) * 8 + r8;
        ab[mf] = smb + (uint32_t)(aoff + row * LDH) * 4u + (uint32_t)((mat >> 1) * 16);
    }
    #pragma unroll
    for (int ks = 0; ks < 8; ++ks) {
        const int kw = ks * 8;                    // word offset
        uint32_t a0[4], a1[4];
        ldsm4(a0, ab[0] + kw * 4);
        ldsm4(a1, ab[1] + kw * 4);
        #pragma unroll
        for (int nf = 0; nf < 8; ++nf) {
            const uint32_t* pb = sB + (n0 + nf * 8 + ar) * LDH + kw + ac;
            uint32_t b0 = pb[0], b1 = pb[4];
            mma_f16(acc[0][nf], a0, b0, b1);
            mma_f16(acc[1][nf], a1, b0, b1);
        }
    }
}

// dual-M GEMM over X: accA += W0cat@X, accP += proj@X (shared B-frags)
__device__ __forceinline__ void gemm_x(uint32_t smb, const uint32_t* __restrict__ sB,
                                       float accA[2][8][4], float accP[2][8][4],
                                       int m0, int n0, int lane) {
    const int ar = lane >> 2, ac = lane & 3;
    const int mat = lane >> 3, r8 = lane & 7;
    uint32_t aw[2], ap[2];
    #pragma unroll
    for (int mf = 0; mf < 2; ++mf) {
        int row = m0 + mf * 16 + (mat & 1) * 8 + r8;
        uint32_t cb = (uint32_t)((mat >> 1) * 16);
        aw[mf] = smb + (uint32_t)(RW0 + row * LDH) * 4u + cb;
        ap[mf] = smb + (uint32_t)(RPJ + row * LDH) * 4u + cb;
    }
    #pragma unroll
    for (int ks = 0; ks < 8; ++ks) {
        const int kw = ks * 8;
        uint32_t a0[4], a1[4], p0[4], p1[4];
        ldsm4(a0, aw[0] + kw * 4);
        ldsm4(a1, aw[1] + kw * 4);
        ldsm4(p0, ap[0] + kw * 4);
        ldsm4(p1, ap[1] + kw * 4);
        #pragma unroll
        for (int nf = 0; nf < 8; ++nf) {
            const uint32_t* pb = sB + (n0 + nf * 8 + ar) * LDH + kw + ac;
            uint32_t b0 = pb[0], b1 = pb[4];
            mma_f16(accA[0][nf], a0, b0, b1);
            mma_f16(accA[1][nf], a1, b0, b1);
            mma_f16(accP[0][nf], p0, b0, b1);
            mma_f16(accP[1][nf], p1, b0, b1);
        }
    }
}

#define ZERO_ACC(A) \
    { _Pragma("unroll") for (int i = 0; i < 2; ++i) \
      _Pragma("unroll") for (int j = 0; j < 8; ++j) \
      _Pragma("unroll") for (int kq = 0; kq < 4; ++kq) (A)[i][j][kq] = 0.f; }

__global__ __launch_bounds__(256, 1) void main_mma_kernel(
    const float* __restrict__ x, const float* __restrict__ sh,
    float* __restrict__ out) {
    extern __shared__ uint32_t smem[];
    const int t = threadIdx.x;
    const int lane = t & 31;
    const int wid = t >> 5;
    const int m0 = (wid >> 1) << 5;          // 0,32,64,96
    const int n0 = (wid & 1) << 6;           // 0,64
    const int b = blockIdx.y;
    const int hw0 = blockIdx.x * 128;

    const int   e0  = g_sel[b * 2],  e1  = g_sel[b * 2 + 1];
    const float ga0 = g_gate[b * 2], ga1 = g_gate[b * 2 + 1];
    const float gs  = g_gsum[b];

    const uint32_t smb = (uint32_t)__cvta_generic_to_shared(smem);
    const uint32_t* w0a = g_w0h + (size_t)e0 * NR * 64;
    const uint32_t* w0b = g_w0h + (size_t)e1 * NR * 64;
    const uint32_t* w1a = g_w1h + (size_t)e0 * NR * 64;
    const uint32_t* w1b = g_w1h + (size_t)e1 * NR * 64;
    const uint32_t* mc0 = g_pw2h + (size_t)e0 * NC * 32;
    const uint32_t* mc1 = g_pw2h + (size_t)e1 * NC * 32;

    const float* xb = x  + (size_t)b * NC * NHW + hw0;
    const float* sb = sh + (size_t)b * NC * NHW + hw0;

    // ---- prologue: queue all 4 weight tiles, stage X + S ----
    #pragma unroll
    for (int i = 0; i < 8; ++i) {        // W0cat
        int cid = t + (i << 8);
        int r = cid >> 4, j = (cid & 15) << 2;
        const uint32_t* src = ((r < 64) ? w0a + r * 64 : w0b + (r - 64) * 64) + j;
        cp16(smb + (uint32_t)(RW0 + r * LDH + j) * 4u, src);
    }
    #pragma unroll
    for (int i = 0; i < 8; ++i) {        // proj
        int cid = t + (i << 8);
        int r = cid >> 4, j = (cid & 15) << 2;
        cp16(smb + (uint32_t)(RPJ + r * LDH + j) * 4u, g_projh + r * 64 + j);
    }
    #pragma unroll
    for (int i = 0; i < 8; ++i) {        // W1cat
        int cid = t + (i << 8);
        int r = cid >> 4, j = (cid & 15) << 2;
        const uint32_t* src = ((r < 64) ? w1a + r * 64 : w1b + (r - 64) * 64) + j;
        cp16(smb + (uint32_t)(RW1 + r * LDH + j) * 4u, src);
    }
    #pragma unroll
    for (int i = 0; i < 8; ++i) {        // Mcat
        int cid = t + (i << 8);
        int r = cid >> 4, j = (cid & 15) << 2;
        const uint32_t* src = (j < 32) ? (mc0 + r * 32 + j) : (mc1 + r * 32 + (j - 32));
        cp16(smb + (uint32_t)(RMC + r * LDH + j) * 4u, src);
    }
    CP_COMMIT();
    stage_act_h(smem + RA, xb, t);
    stage_act_h(smem + RS, sb, t);
    CP_WAIT0();
    __syncthreads();

    float accA[2][8][4]; ZERO_ACC(accA);
    float accP[2][8][4]; ZERO_ACC(accP);
    float accG[2][8][4]; ZERO_ACC(accG);

    // GEMM X (dual-M): accA = W0cat @ X, accP = proj @ X
    gemm_x(smb, smem + RA, accA, accP, m0, n0, lane);
    // GEMM S: accG = W1cat @ S
    gemm_1(smb, RW1, smem + RS, accG, m0, n0, lane);
    __syncthreads();                     // all warps done reading X (RA)

    // T = ga(row) * accA * silu(accG) -> RA as [px][rank halves]
    {
        const int ar = lane >> 2, ac = lane & 3;
        __half* th = (__half*)(smem + RA);
        #pragma unroll
        for (int mf = 0; mf < 2; ++mf) {
            const float ga = ((m0 + mf * 16) < 64) ? ga0 : ga1;
            #pragma unroll
            for (int nf = 0; nf < 8; ++nf) {
                const int col = n0 + nf * 8 + 2 * ac;
                #pragma unroll
                for (int half = 0; half < 2; ++half) {
                    const int row = m0 + mf * 16 + ar + half * 8;
                    float a0 = accA[mf][nf][half * 2 + 0];
                    float a1 = accA[mf][nf][half * 2 + 1];
                    float g0 = accG[mf][nf][half * 2 + 0];
                    float g1 = accG[mf][nf][half * 2 + 1];
                    th[col * 136 + row]       = __float2half_rn(ga * a0 * (g0 / (1.f + __expf(-g0))));
                    th[(col + 1) * 136 + row] = __float2half_rn(ga * a1 * (g1 / (1.f + __expf(-g1))));
                }
            }
        }
    }
    ZERO_ACC(accA);                      // reuse as accO
    __syncthreads();

    // GEMM T: accO = Mcat @ T
    gemm_1(smb, RMC, smem + RA, accA, m0, n0, lane);

    // epilogue: out = accO + gs * accP
    {
        const int ar = lane >> 2, ac = lane & 3;
        float* ob = out + (size_t)b * NC * NHW + hw0;
        #pragma unroll
        for (int mf = 0; mf < 2; ++mf) {
            #pragma unroll
            for (int nf = 0; nf < 8; ++nf) {
                const int col = n0 + nf * 8 + 2 * ac;
                #pragma unroll
                for (int half = 0; half < 2; ++half) {
                    const int row = m0 + mf * 16 + ar + half * 8;
                    float2 v = make_float2(
                        accA[mf][nf][half * 2 + 0] + gs * accP[mf][nf][half * 2 + 0],
                        accA[mf][nf][half * 2 + 1] + gs * accP[mf][nf][half * 2 + 1]);
                    *(float2*)(ob + (size_t)row * NHW + col) = v;
                }
            }
        }
    }
}

// ---------------------------------------------------------------------------
extern "C" void kernel_launch(void* const* d_in, const int* in_sizes, int n_in,
                              void* d_out, int out_size) {
    const float* x       = (const float*)d_in[0];
    const float* sh      = (const float*)d_in[1];
    const float* mlp_w1  = (const float*)d_in[2];
    const float* mlp_b1  = (const float*)d_in[3];
    const float* mlp_w2  = (const float*)d_in[4];
    const float* mlp_b2  = (const float*)d_in[5];
    const float* gate_w  = (const float*)d_in[6];
    const float* fgate_w = (const float*)d_in[7];
    const float* exp_w0  = (const float*)d_in[8];
    const float* exp_w1  = (const float*)d_in[9];
    const float* exp_w2  = (const float*)d_in[10];
    const float* proj_w  = (const float*)d_in[11];
    float* out = (float*)d_out;

    cudaFuncSetAttribute(main_mma_kernel, cudaFuncAttributeMaxDynamicSharedMemorySize, SMEM_MAIN);

    conv_pw2_kernel<<<660, 256>>>(x, exp_w2, proj_w, exp_w0, exp_w1);
    routing_kernel<<<NB, 256>>>(mlp_w1, mlp_b1, mlp_w2, mlp_b2, gate_w, fgate_w);
    main_mma_kernel<<<dim3(NHW / 128, NB), 256, SMEM_MAIN>>>(x, sh, out);
}

// round 16
// speedup vs baseline: 1.9577x; 1.0395x over previous
#include <cuda_runtime.h>
#include <cuda_fp16.h>
#include <math.h>
#include <stdint.h>

// Problem constants
#define NB 8
#define NC 128
#define NHW 16384
#define NE 4
#define NR 64

// All main-kernel tiles: 128 rows x 68 words (136 halves). Word offsets:
#define LDH 68
#define RA  0        // X' acts [px][k] (gs-scaled)
#define RS  8704     // S acts [px][k]  (later reused for T)
#define RW0 17408    // W0cat  [m][k]
#define RPJ 26112    // proj   [m][k]
#define RW1 34816    // W1cat  [m][k]
#define RMC 43520    // Mcat   [d][rank]
#define SMEM_MAIN (52224 * 4)   // 208896 bytes

// ---------------- device scratch ----------------
__device__ float g_fe0[NB * NC];
__device__ float g_pooled[NB * NC];
__device__ int   g_sel[NB * 2];
__device__ float g_gate[NB * 2];
__device__ float g_gsum[NB];
// pre-converted fp16 weights (packed half2 words, +slack for cp alignment)
__device__ __align__(16) uint32_t g_w0h[NE * NR * 64 + 8];   // [e][r][64w]
__device__ __align__(16) uint32_t g_w1h[NE * NR * 64 + 8];
__device__ __align__(16) uint32_t g_pw2h[NE * NC * 32 + 8];  // [e][d][32w]
__device__ __align__(16) uint32_t g_projh[NC * 64 + 8];      // [d][64w]

__device__ __forceinline__ float gelu_f(float v) {
    return 0.5f * v * (1.0f + erff(v * 0.70710678118654752440f));
}
__device__ __forceinline__ float gelu_fast(float v) {
    float u = 0.7978845608f * (v + 0.044715f * v * v * v);
    float th;
    asm("tanh.approx.f32 %0, %1;" : "=f"(th) : "f"(u));
    return 0.5f * v * (1.0f + th);
}
__device__ __forceinline__ uint32_t pack2(float a, float b) {
    __half2 h = __floats2half2_rn(a, b);
    return *(uint32_t*)&h;
}
__device__ __forceinline__ void mma_f16(float* c, const uint32_t* a, uint32_t b0, uint32_t b1) {
    asm volatile(
        "mma.sync.aligned.m16n8k16.row.col.f32.f16.f16.f32 "
        "{%0,%1,%2,%3}, {%4,%5,%6,%7}, {%8,%9}, {%0,%1,%2,%3};"
        : "+f"(c[0]), "+f"(c[1]), "+f"(c[2]), "+f"(c[3])
        : "r"(a[0]), "r"(a[1]), "r"(a[2]), "r"(a[3]), "r"(b0), "r"(b1));
}
__device__ __forceinline__ void ldsm4(uint32_t* r, uint32_t saddr) {
    asm volatile("ldmatrix.sync.aligned.m8n8.x4.shared.b16 {%0,%1,%2,%3}, [%4];"
        : "=r"(r[0]), "=r"(r[1]), "=r"(r[2]), "=r"(r[3]) : "r"(saddr));
}
__device__ __forceinline__ void cp16(uint32_t saddr, const uint32_t* g) {
    asm volatile("{ .reg .u64 ga; cvta.to.global.u64 ga, %1; "
                 "cp.async.ca.shared.global [%0], [ga], 16; }"
                 :: "r"(saddr), "l"(g) : "memory");
}
#define CP_COMMIT() asm volatile("cp.async.commit_group;" ::: "memory")
#define CP_WAIT0()  asm volatile("cp.async.wait_group 0;" ::: "memory")

// ---------------------------------------------------------------------------
// Kernel 1 (fused): [0,512) conv stencil; [512,640) PW2 -> fp16;
//   [640,660) fp16 pack of exp_w0 / exp_w1 / proj_w.
// ---------------------------------------------------------------------------
__global__ __launch_bounds__(256) void conv_pw2_kernel(
    const float* __restrict__ x, const float* __restrict__ exp_w2,
    const float* __restrict__ proj_w, const float* __restrict__ exp_w0,
    const float* __restrict__ exp_w1) {
    const int t = threadIdx.x;
    if (blockIdx.x >= 640) {
        int c = blockIdx.x - 640;
        const float* src;
        uint32_t* dst;
        if (c < 8)       { src = exp_w0 + c * 4096;        dst = g_w0h + c * 2048; }
        else if (c < 16) { src = exp_w1 + (c - 8) * 4096;  dst = g_w1h + (c - 8) * 2048; }
        else             { src = proj_w + (c - 16) * 4096; dst = g_projh + (c - 16) * 2048; }
        #pragma unroll
        for (int i = 0; i < 4; ++i) {
            int f = t + (i << 8);
            float4 u = ((const float4*)src)[f];
            uint2 w;
            w.x = pack2(u.x, u.y);
            w.y = pack2(u.z, u.w);
            ((uint2*)dst)[f] = w;
        }
        return;
    }
    if (blockIdx.x >= 512) {
        int bi = blockIdx.x - 512;
        int e = bi >> 5;
        int d = ((bi & 31) << 2) + (t >> 6);
        int r = t & 63;
        const float* pw = proj_w + d * NC;
        const float* w2 = exp_w2 + (size_t)e * NC * NR + r;
        float a = 0.f;
        #pragma unroll 8
        for (int c = 0; c < NC; ++c) a += pw[c] * w2[c * NR];
        ((__half*)g_pw2h)[(e * NC + d) * NR + r] = __float2half_rn(a);
        return;
    }

    // ---- conv stencil: 2 planes/block, rolling registers, shfl halos ----
    const int wid = t >> 5, lane = t & 31;
    const int plane = blockIdx.x * 2 + (wid >> 2);
    const int w4 = wid & 3;
    const float* p = x + (size_t)plane * NHW + lane * 4;
    const int r0 = w4 * 32;

    const float4 z = make_float4(0.f, 0.f, 0.f, 0.f);
    float4 prev = (r0 > 0) ? *(const float4*)(p + (r0 - 1) * 128) : z;
    float4 cur  = *(const float4*)(p + r0 * 128);
    float4 nxt  = *(const float4*)(p + (r0 + 1) * 128);
    float4 nxt2 = *(const float4*)(p + (r0 + 2) * 128);

    float sumg = 0.f, sumx = 0.f;
    #pragma unroll 4
    for (int i = 0; i < 32; ++i) {
        int rn = r0 + i + 3;
        float4 inc = (rn < 128) ? *(const float4*)(p + rn * 128) : z;

        sumx += cur.x + cur.y + cur.z + cur.w;

        float pl = __shfl_up_sync(0xffffffffu, prev.w, 1);
        float cl = __shfl_up_sync(0xffffffffu, cur.w, 1);
        float nl = __shfl_up_sync(0xffffffffu, nxt.w, 1);
        float pr = __shfl_down_sync(0xffffffffu, prev.x, 1);
        float cr = __shfl_down_sync(0xffffffffu, cur.x, 1);
        float nr = __shfl_down_sync(0xffffffffu, nxt.x, 1);
        if (lane == 0)  { pl = 0.f; cl = 0.f; nl = 0.f; }
        if (lane == 31) { pr = 0.f; cr = 0.f; nr = 0.f; }

        float nb0 = pl + prev.x + prev.y + cl + cur.y + nl + nxt.x + nxt.y;
        float nb1 = prev.x + prev.y + prev.z + cur.x + cur.z + nxt.x + nxt.y + nxt.z;
        float nb2 = prev.y + prev.z + prev.w + cur.y + cur.w + nxt.y + nxt.z + nxt.w;
        float nb3 = prev.z + prev.w + pr + cur.z + cr + nxt.z + nxt.w + nr;

        sumg += gelu_fast(8.f * cur.x - nb0);
        sumg += gelu_fast(8.f * cur.y - nb1);
        sumg += gelu_fast(8.f * cur.z - nb2);
        sumg += gelu_fast(8.f * cur.w - nb3);

        prev = cur; cur = nxt; nxt = nxt2; nxt2 = inc;
    }

    for (int o = 16; o > 0; o >>= 1) {
        sumg += __shfl_down_sync(0xffffffffu, sumg, o);
        sumx += __shfl_down_sync(0xffffffffu, sumx, o);
    }
    __shared__ float rg[8], rx[8];
    if (lane == 0) { rg[wid] = sumg; rx[wid] = sumx; }
    __syncthreads();
    if (t < 2) {
        float ag = 0.f, ax = 0.f;
        #pragma unroll
        for (int i = 0; i < 4; ++i) { ag += rg[t * 4 + i]; ax += rx[t * 4 + i]; }
        const float inv = 1.0f / 16384.0f;
        int pl = blockIdx.x * 2 + t;
        g_fe0[pl]    = ag * inv;
        g_pooled[pl] = ax * inv;
    }
}

// ---------------------------------------------------------------------------
// Kernel 2: routing, one block per batch
// ---------------------------------------------------------------------------
__global__ __launch_bounds__(256) void routing_kernel(
    const float* __restrict__ mlp_w1, const float* __restrict__ mlp_b1,
    const float* __restrict__ mlp_w2, const float* __restrict__ mlp_b2,
    const float* __restrict__ gate_w, const float* __restrict__ fgate_w) {
    __shared__ float s_in[NC], s_pool[NC], s_h1[256], s_fe[NC], s_log[NE];
    const int b = blockIdx.x;
    const int t = threadIdx.x;

    if (t < NC) { s_in[t] = g_fe0[b * NC + t]; s_pool[t] = g_pooled[b * NC + t]; }
    __syncthreads();
    {
        float a = mlp_b1[t];
        #pragma unroll 8
        for (int c = 0; c < NC; ++c) a += s_in[c] * mlp_w1[c * 256 + t];
        s_h1[t] = gelu_f(a);
    }
    __syncthreads();
    if (t < NC) {
        float a = mlp_b2[t];
        #pragma unroll 8
        for (int c = 0; c < 256; ++c) a += s_h1[c] * mlp_w2[c * NC + t];
        s_fe[t] = a;
    }
    __syncthreads();
    if (t < NE) {
        float a = 0.f;
        for (int c = 0; c < NC; ++c)
            a += s_pool[c] * gate_w[c * NE + t] + s_fe[c] * fgate_w[c * NE + t];
        s_log[t] = a;
    }
    __syncthreads();
    if (t == 0) {
        float sc[NE];
        float m = -1e30f;
        #pragma unroll
        for (int e = 0; e < NE; ++e) { sc[e] = s_log[e]; m = fmaxf(m, sc[e]); }
        float ss = 0.f;
        #pragma unroll
        for (int e = 0; e < NE; ++e) { sc[e] = expf(sc[e] - m); ss += sc[e]; }
        float inv = 1.0f / ss;
        #pragma unroll
        for (int e = 0; e < NE; ++e) sc[e] *= inv;
        int i0 = 0;
        #pragma unroll
        for (int e = 1; e < NE; ++e) if (sc[e] > sc[i0]) i0 = e;
        int i1 = -1;
        #pragma unroll
        for (int e = 0; e < NE; ++e) {
            if (e == i0) continue;
            if (i1 < 0 || sc[e] > sc[i1]) i1 = e;
        }
        g_sel[b * 2] = i0;  g_sel[b * 2 + 1] = i1;
        g_gate[b * 2] = sc[i0]; g_gate[b * 2 + 1] = sc[i1];
        g_gsum[b] = sc[i0] + sc[i1];
    }
}

// ---------------------------------------------------------------------------
// Main fp16 tensor-core kernel: 512 threads, 16 warps (4M x 4N of 32x32),
// single-accumulator K=256 final GEMM (proj folded via X' = gs*X).
// ---------------------------------------------------------------------------

// stage activations [128 c][128 px] f32 -> [px][k packed half2], scaled
__device__ __forceinline__ void stage_act_h(uint32_t* smw, const float* __restrict__ gsrc,
                                            float sc, int t) {
    #pragma unroll
    for (int i = 0; i < 8; ++i) {
        int unit = t + (i << 9);
        int px = (unit & 31) + 32 * ((unit >> 5) & 3);
        int cq = unit >> 7;                        // 0..31, c = 4cq..4cq+3
        const float* g = gsrc + (size_t)(4 * cq) * NHW + px;
        float v0 = g[0] * sc;
        float v1 = g[NHW] * sc;
        float v2 = g[2 * NHW] * sc;
        float v3 = g[3 * NHW] * sc;
        uint2 w;
        w.x = pack2(v0, v1);
        w.y = pack2(v2, v3);
        *(uint2*)(smw + px * LDH + 2 * cq) = w;
    }
}

// one M=32/N=32 GEMM pass: acc += W[m][k] * B[k][n]  (fp16, K=128)
__device__ __forceinline__ void gemm_1(uint32_t smb, int aoff, const uint32_t* __restrict__ sB,
                                       float acc[2][4][4], int m0, int n0, int lane) {
    const int ar = lane >> 2, ac = lane & 3;
    const int mat = lane >> 3, r8 = lane & 7;
    uint32_t ab[2];
    #pragma unroll
    for (int mf = 0; mf < 2; ++mf) {
        int row = m0 + mf * 16 + (mat & 1) * 8 + r8;
        ab[mf] = smb + (uint32_t)(aoff + row * LDH) * 4u + (uint32_t)((mat >> 1) * 16);
    }
    #pragma unroll
    for (int ks = 0; ks < 8; ++ks) {
        const int kw = ks * 8;                    // word offset
        uint32_t a0[4], a1[4];
        ldsm4(a0, ab[0] + kw * 4);
        ldsm4(a1, ab[1] + kw * 4);
        #pragma unroll
        for (int nf = 0; nf < 4; ++nf) {
            const uint32_t* pb = sB + (n0 + nf * 8 + ar) * LDH + kw + ac;
            uint32_t b0 = pb[0], b1 = pb[4];
            mma_f16(acc[0][nf], a0, b0, b1);
            mma_f16(acc[1][nf], a1, b0, b1);
        }
    }
}

#define ZERO_ACC(A) \
    { _Pragma("unroll") for (int i = 0; i < 2; ++i) \
      _Pragma("unroll") for (int j = 0; j < 4; ++j) \
      _Pragma("unroll") for (int kq = 0; kq < 4; ++kq) (A)[i][j][kq] = 0.f; }

__global__ __launch_bounds__(512, 1) void main_mma_kernel(
    const float* __restrict__ x, const float* __restrict__ sh,
    float* __restrict__ out) {
    extern __shared__ uint32_t smem[];
    const int t = threadIdx.x;
    const int lane = t & 31;
    const int wid = t >> 5;
    const int m0 = (wid >> 2) << 5;          // 0,32,64,96
    const int n0 = (wid & 3) << 5;           // 0,32,64,96
    const int b = blockIdx.y;
    const int hw0 = blockIdx.x * 128;

    const int   e0  = g_sel[b * 2],  e1  = g_sel[b * 2 + 1];
    const float ga0 = g_gate[b * 2], ga1 = g_gate[b * 2 + 1];
    const float gs  = g_gsum[b];
    const float igs = 1.0f / gs;

    const uint32_t smb = (uint32_t)__cvta_generic_to_shared(smem);
    const uint32_t* w0a = g_w0h + (size_t)e0 * NR * 64;
    const uint32_t* w0b = g_w0h + (size_t)e1 * NR * 64;
    const uint32_t* w1a = g_w1h + (size_t)e0 * NR * 64;
    const uint32_t* w1b = g_w1h + (size_t)e1 * NR * 64;
    const uint32_t* mc0 = g_pw2h + (size_t)e0 * NC * 32;
    const uint32_t* mc1 = g_pw2h + (size_t)e1 * NC * 32;

    const float* xb = x  + (size_t)b * NC * NHW + hw0;
    const float* sb = sh + (size_t)b * NC * NHW + hw0;

    // ---- prologue: queue all 4 weight tiles, stage X' (gs-scaled) + S ----
    #pragma unroll
    for (int i = 0; i < 4; ++i) {        // W0cat
        int cid = t + (i << 9);
        int r = cid >> 4, j = (cid & 15) << 2;
        const uint32_t* src = ((r < 64) ? w0a + r * 64 : w0b + (r - 64) * 64) + j;
        cp16(smb + (uint32_t)(RW0 + r * LDH + j) * 4u, src);
    }
    #pragma unroll
    for (int i = 0; i < 4; ++i) {        // proj
        int cid = t + (i << 9);
        int r = cid >> 4, j = (cid & 15) << 2;
        cp16(smb + (uint32_t)(RPJ + r * LDH + j) * 4u, g_projh + r * 64 + j);
    }
    #pragma unroll
    for (int i = 0; i < 4; ++i) {        // W1cat
        int cid = t + (i << 9);
        int r = cid >> 4, j = (cid & 15) << 2;
        const uint32_t* src = ((r < 64) ? w1a + r * 64 : w1b + (r - 64) * 64) + j;
        cp16(smb + (uint32_t)(RW1 + r * LDH + j) * 4u, src);
    }
    #pragma unroll
    for (int i = 0; i < 4; ++i) {        // Mcat
        int cid = t + (i << 9);
        int r = cid >> 4, j = (cid & 15) << 2;
        const uint32_t* src = (j < 32) ? (mc0 + r * 32 + j) : (mc1 + r * 32 + (j - 32));
        cp16(smb + (uint32_t)(RMC + r * LDH + j) * 4u, src);
    }
    CP_COMMIT();
    stage_act_h(smem + RA, xb, gs, t);
    stage_act_h(smem + RS, sb, 1.0f, t);
    CP_WAIT0();
    __syncthreads();

    float accA[2][4][4]; ZERO_ACC(accA);
    float accG[2][4][4]; ZERO_ACC(accG);

    // GEMM1: accA = W0cat @ X'   ;   GEMM2: accG = W1cat @ S
    gemm_1(smb, RW0, smem + RA, accA, m0, n0, lane);
    gemm_1(smb, RW1, smem + RS, accG, m0, n0, lane);
    __syncthreads();                     // all warps done reading S (RS)

    // T = ga(row)/gs * accA * silu(accG) -> RS as [px][rank halves]
    {
        const int ar = lane >> 2, ac = lane & 3;
        __half* th = (__half*)(smem + RS);
        #pragma unroll
        for (int mf = 0; mf < 2; ++mf) {
            const float ga = (((m0 + mf * 16) < 64) ? ga0 : ga1) * igs;
            #pragma unroll
            for (int nf = 0; nf < 4; ++nf) {
                const int col = n0 + nf * 8 + 2 * ac;
                #pragma unroll
                for (int half = 0; half < 2; ++half) {
                    const int row = m0 + mf * 16 + ar + half * 8;
                    float a0 = accA[mf][nf][half * 2 + 0];
                    float a1 = accA[mf][nf][half * 2 + 1];
                    float g0 = accG[mf][nf][half * 2 + 0];
                    float g1 = accG[mf][nf][half * 2 + 1];
                    th[col * 136 + row]       = __float2half_rn(ga * a0 * (g0 / (1.f + __expf(-g0))));
                    th[(col + 1) * 136 + row] = __float2half_rn(ga * a1 * (g1 / (1.f + __expf(-g1))));
                }
            }
        }
    }
    ZERO_ACC(accA);                      // reuse as accO
    __syncthreads();

    // GEMM3 (K=256, single accumulator): accO = Mcat @ T + proj @ X'
    gemm_1(smb, RMC, smem + RS, accA, m0, n0, lane);
    gemm_1(smb, RPJ, smem + RA, accA, m0, n0, lane);

    // epilogue: out = accO
    {
        const int ar = lane >> 2, ac = lane & 3;
        float* ob = out + (size_t)b * NC * NHW + hw0;
        #pragma unroll
        for (int mf = 0; mf < 2; ++mf) {
            #pragma unroll
            for (int nf = 0; nf < 4; ++nf) {
                const int col = n0 + nf * 8 + 2 * ac;
                #pragma unroll
                for (int half = 0; half < 2; ++half) {
                    const int row = m0 + mf * 16 + ar + half * 8;
                    float2 v = make_float2(accA[mf][nf][half * 2 + 0],
                                           accA[mf][nf][half * 2 + 1]);
                    *(float2*)(ob + (size_t)row * NHW + col) = v;
                }
            }
        }
    }
}

// ---------------------------------------------------------------------------
extern "C" void kernel_launch(void* const* d_in, const int* in_sizes, int n_in,
                              void* d_out, int out_size) {
    const float* x       = (const float*)d_in[0];
    const float* sh      = (const float*)d_in[1];
    const float* mlp_w1  = (const float*)d_in[2];
    const float* mlp_b1  = (const float*)d_in[3];
    const float* mlp_w2  = (const float*)d_in[4];
    const float* mlp_b2  = (const float*)d_in[5];
    const float* gate_w  = (const float*)d_in[6];
    const float* fgate_w = (const float*)d_in[7];
    const float* exp_w0  = (const float*)d_in[8];
    const float* exp_w1  = (const float*)d_in[9];
    const float* exp_w2  = (const float*)d_in[10];
    const float* proj_w  = (const float*)d_in[11];
    float* out = (float*)d_out;

    cudaFuncSetAttribute(main_mma_kernel, cudaFuncAttributeMaxDynamicSharedMemorySize, SMEM_MAIN);

    conv_pw2_kernel<<<660, 256>>>(x, exp_w2, proj_w, exp_w0, exp_w1);
    routing_kernel<<<NB, 256>>>(mlp_w1, mlp_b1, mlp_w2, mlp_b2, gate_w, fgate_w);
    main_mma_kernel<<<dim3(NHW / 128, NB), 512, SMEM_MAIN>>>(x, sh, out);
}